// round 4
// baseline (speedup 1.0000x reference)
#include <cuda_runtime.h>
#include <cstdint>

#define N_NODES 100000
#define N_EDGES 3200000
#define BN_EPS 1e-5f
#define SLOPE 0.01f

// ---------------- scratch (static device globals; no allocation) ----------------
__device__ float g_deg[N_NODES];
__device__ float g_dinv[N_NODES];
__device__ int   g_src[N_EDGES];                 // 12.8 MB
__device__ int   g_dst[N_EDGES];                 // 12.8 MB
__device__ int   g_is64;
__device__ float g_xw1[(size_t)N_NODES * 256];   // 102.4 MB
__device__ float g_h1 [(size_t)N_NODES * 256];   // 102.4 MB
__device__ float g_xw2[(size_t)N_NODES * 512];   // 204.8 MB
__device__ float g_h2 [(size_t)N_NODES * 512];   // 204.8 MB
__device__ float g_colsum[512];
__device__ float g_colsq [512];
__device__ float g_scale [512];
__device__ float g_shift [512];

// ---------------- edge dtype detection + conversion ----------------
// If the harness narrowed int64 -> int32, reading the buffer as u64 packs two
// indices per word; with random indices < 1e5 the high half is nonzero almost
// surely within 4096 samples. A real int64 index array stays < N_NODES.
__global__ void detect_k(const unsigned long long* __restrict__ p) {
    __shared__ int bad;
    if (threadIdx.x == 0) bad = 0;
    __syncthreads();
    for (int i = threadIdx.x; i < 4096; i += 256)
        if (p[i] >= (unsigned long long)N_NODES) bad = 1;
    __syncthreads();
    if (threadIdx.x == 0) g_is64 = bad ? 0 : 1;
}
__global__ void cvt_edges_k(const void* __restrict__ ei) {
    int e = blockIdx.x * blockDim.x + threadIdx.x;
    if (e >= N_EDGES) return;
    if (g_is64) {
        const long long* p = (const long long*)ei;
        g_src[e] = (int)p[e];
        g_dst[e] = (int)p[e + N_EDGES];
    } else {
        const int* p = (const int*)ei;
        g_src[e] = p[e];
        g_dst[e] = p[e + N_EDGES];
    }
}

// ---------------- degree / norm ----------------
__global__ void deg_init_k() {
    int i = blockIdx.x * blockDim.x + threadIdx.x;
    if (i < N_NODES) g_deg[i] = 1.0f;   // self-loop
}
__global__ void deg_count_k() {
    int e = blockIdx.x * blockDim.x + threadIdx.x;
    if (e < N_EDGES) atomicAdd(&g_deg[g_dst[e]], 1.0f);
}
__global__ void dinv_k() {
    int i = blockIdx.x * blockDim.x + threadIdx.x;
    if (i < N_NODES) {
        float d = g_deg[i];
        g_dinv[i] = d > 0.f ? rsqrtf(d) : 0.f;
    }
}

// ---------------- SGEMM: C[M,Nn] = A[M,K] @ B[K,Nn]; Nn%128==0, K%8==0 ----------------
// SELFLOOP epilogue: additionally writes H[r,:] = C[r,:] * dinv[r]^2
template <bool SELFLOOP>
__global__ __launch_bounds__(256)
void sgemm128(const float* __restrict__ A, const float* __restrict__ B,
              float* __restrict__ C, float* __restrict__ H,
              int M, int Nn, int K) {
    __shared__ float As[8][128];
    __shared__ float Bs[8][128];
    const int tid = threadIdx.x;
    const int blockRow = blockIdx.y, blockCol = blockIdx.x;
    const int tRow = tid / 16, tCol = tid % 16;
    const int aRow = tid / 2, aCol = (tid % 2) * 4;
    const int bRow = tid / 32, bCol = (tid % 32) * 4;
    const int rowBase = blockRow * 128;

    float acc[8][8];
#pragma unroll
    for (int i = 0; i < 8; i++)
#pragma unroll
        for (int j = 0; j < 8; j++) acc[i][j] = 0.f;

    for (int k0 = 0; k0 < K; k0 += 8) {
        int gr = rowBase + aRow;
        float4 a = make_float4(0.f, 0.f, 0.f, 0.f);
        if (gr < M) a = *reinterpret_cast<const float4*>(&A[(size_t)gr * K + k0 + aCol]);
        As[aCol + 0][aRow] = a.x;
        As[aCol + 1][aRow] = a.y;
        As[aCol + 2][aRow] = a.z;
        As[aCol + 3][aRow] = a.w;
        float4 b = *reinterpret_cast<const float4*>(
            &B[(size_t)(k0 + bRow) * Nn + blockCol * 128 + bCol]);
        *reinterpret_cast<float4*>(&Bs[bRow][bCol]) = b;
        __syncthreads();
#pragma unroll
        for (int k = 0; k < 8; k++) {
            float rm[8], rn[8];
            *(float4*)&rm[0] = *(float4*)&As[k][tRow * 8];
            *(float4*)&rm[4] = *(float4*)&As[k][tRow * 8 + 4];
            *(float4*)&rn[0] = *(float4*)&Bs[k][tCol * 8];
            *(float4*)&rn[4] = *(float4*)&Bs[k][tCol * 8 + 4];
#pragma unroll
            for (int i = 0; i < 8; i++)
#pragma unroll
                for (int j = 0; j < 8; j++) acc[i][j] += rm[i] * rn[j];
        }
        __syncthreads();
    }

    const int colBase = blockCol * 128 + tCol * 8;
#pragma unroll
    for (int i = 0; i < 8; i++) {
        int r = rowBase + tRow * 8 + i;
        if (r < M) {
            *reinterpret_cast<float4*>(&C[(size_t)r * Nn + colBase])     = *(float4*)&acc[i][0];
            *reinterpret_cast<float4*>(&C[(size_t)r * Nn + colBase + 4]) = *(float4*)&acc[i][4];
            if (SELFLOOP) {
                float di = g_dinv[r];
                float s = di * di;
                float v[8];
#pragma unroll
                for (int j = 0; j < 8; j++) v[j] = acc[i][j] * s;
                *reinterpret_cast<float4*>(&H[(size_t)r * Nn + colBase])     = *(float4*)&v[0];
                *reinterpret_cast<float4*>(&H[(size_t)r * Nn + colBase + 4]) = *(float4*)&v[4];
            }
        }
    }
}

// ---------------- edge aggregation: h[dst] += xw[src]*dinv[src]*dinv[dst] ----------------
// warp per edge; float4 source reads, scalar float atomics to dst row.
template <int C>
__global__ __launch_bounds__(256)
void aggregate_k(const float* __restrict__ xw, float* __restrict__ h) {
    int warp = (blockIdx.x * blockDim.x + threadIdx.x) >> 5;
    int lane = threadIdx.x & 31;
    if (warp >= N_EDGES) return;
    int s = g_src[warp];
    int d = g_dst[warp];
    float nrm = g_dinv[s] * g_dinv[d];
    const float4* xr = reinterpret_cast<const float4*>(xw + (size_t)s * C);
    float* hr = h + (size_t)d * C;
#pragma unroll
    for (int c = lane; c < C / 4; c += 32) {
        float4 v = xr[c];
        atomicAdd(&hr[c * 4 + 0], v.x * nrm);
        atomicAdd(&hr[c * 4 + 1], v.y * nrm);
        atomicAdd(&hr[c * 4 + 2], v.z * nrm);
        atomicAdd(&hr[c * 4 + 3], v.w * nrm);
    }
}

// ---------------- BatchNorm ----------------
__global__ void bn_zero_k(int C) {
    int c = threadIdx.x + blockIdx.x * blockDim.x;
    if (c < C) { g_colsum[c] = 0.f; g_colsq[c] = 0.f; }
}
template <int C>
__global__ void bn_reduce_k(const float* __restrict__ h) {
    int c = threadIdx.x;  // blockDim == C
    int rows_per = (N_NODES + gridDim.x - 1) / gridDim.x;
    int r0 = blockIdx.x * rows_per;
    int r1 = min(r0 + rows_per, N_NODES);
    float s = 0.f, sq = 0.f;
    for (int r = r0; r < r1; r++) {
        float v = h[(size_t)r * C + c];
        s += v; sq += v * v;
    }
    atomicAdd(&g_colsum[c], s);
    atomicAdd(&g_colsq[c], sq);
}
__global__ void bn_scale_k(const float* __restrict__ g, const float* __restrict__ be, int C) {
    int c = threadIdx.x + blockIdx.x * blockDim.x;
    if (c < C) {
        float mean = g_colsum[c] * (1.0f / N_NODES);
        float var  = g_colsq[c] * (1.0f / N_NODES) - mean * mean;
        float a = g[c] * rsqrtf(var + BN_EPS);
        g_scale[c] = a;
        g_shift[c] = be[c] - mean * a;
    }
}
template <int C>
__global__ void bn_apply_k(float* __restrict__ h) {
    size_t idx = (size_t)blockIdx.x * blockDim.x + threadIdx.x;
    if (idx < (size_t)N_NODES * C) {
        int c = (int)(idx & (C - 1));
        float v = h[idx] * g_scale[c] + g_shift[c];
        h[idx] = v >= 0.f ? v : SLOPE * v;
    }
}

// ---------------- fused dense1 + LeakyReLU + dense2 + softmax ----------------
__global__ __launch_bounds__(256)
void dense_fused_k(const float* __restrict__ A,    // h2 [M,512]
                   const float* __restrict__ Wd1,  // [512,4096]
                   const float* __restrict__ bd1,  // [4096]
                   const float* __restrict__ Wd2,  // [4096,6]
                   const float* __restrict__ bd2,  // [6]
                   float* __restrict__ out, int M) {
    __shared__ float As[8][128];
    __shared__ float Bs[8][128];
    __shared__ float W2s[128][6];
    __shared__ float rowacc[128][6];
    const int tid = threadIdx.x;
    const int tRow = tid / 16, tCol = tid % 16;
    const int aRow = tid / 2, aCol = (tid % 2) * 4;
    const int bRow = tid / 32, bCol = (tid % 32) * 4;
    const int rowBase = blockIdx.x * 128;

    float acc6[8][6];
#pragma unroll
    for (int i = 0; i < 8; i++)
#pragma unroll
        for (int j = 0; j < 6; j++) acc6[i][j] = 0.f;

    for (int n0 = 0; n0 < 4096; n0 += 128) {
        float acc[8][8];
#pragma unroll
        for (int i = 0; i < 8; i++)
#pragma unroll
            for (int j = 0; j < 8; j++) acc[i][j] = 0.f;

        for (int k0 = 0; k0 < 512; k0 += 8) {
            int gr = rowBase + aRow;
            float4 a = make_float4(0.f, 0.f, 0.f, 0.f);
            if (gr < M) a = *reinterpret_cast<const float4*>(&A[(size_t)gr * 512 + k0 + aCol]);
            As[aCol + 0][aRow] = a.x;
            As[aCol + 1][aRow] = a.y;
            As[aCol + 2][aRow] = a.z;
            As[aCol + 3][aRow] = a.w;
            float4 b = *reinterpret_cast<const float4*>(
                &Wd1[(size_t)(k0 + bRow) * 4096 + n0 + bCol]);
            *reinterpret_cast<float4*>(&Bs[bRow][bCol]) = b;
            __syncthreads();
#pragma unroll
            for (int k = 0; k < 8; k++) {
                float rm[8], rn[8];
                *(float4*)&rm[0] = *(float4*)&As[k][tRow * 8];
                *(float4*)&rm[4] = *(float4*)&As[k][tRow * 8 + 4];
                *(float4*)&rn[0] = *(float4*)&Bs[k][tCol * 8];
                *(float4*)&rn[4] = *(float4*)&Bs[k][tCol * 8 + 4];
#pragma unroll
                for (int i = 0; i < 8; i++)
#pragma unroll
                    for (int j = 0; j < 8; j++) acc[i][j] += rm[i] * rn[j];
            }
            __syncthreads();
        }

        // load Wd2 tile for this n-range (128 x 6 = 768 floats)
        for (int i = tid; i < 768; i += 256)
            W2s[i / 6][i % 6] = Wd2[(size_t)(n0 + i / 6) * 6 + (i % 6)];
        __syncthreads();

        // epilogue: bias + leakyrelu, contract against Wd2 tile
#pragma unroll
        for (int j = 0; j < 8; j++) {
            int nc = tCol * 8 + j;
            float bj = bd1[n0 + nc];
#pragma unroll
            for (int i = 0; i < 8; i++) {
                float t = acc[i][j] + bj;
                t = t >= 0.f ? t : SLOPE * t;
#pragma unroll
                for (int j6 = 0; j6 < 6; j6++)
                    acc6[i][j6] += t * W2s[nc][j6];
            }
        }
        __syncthreads();  // before next n-tile overwrites smem
    }

    // cross-thread (tCol) reduction into rowacc
    for (int i = tid; i < 768; i += 256)
        ((float*)rowacc)[i] = 0.f;
    __syncthreads();
#pragma unroll
    for (int i = 0; i < 8; i++)
#pragma unroll
        for (int j6 = 0; j6 < 6; j6++)
            atomicAdd(&rowacc[tRow * 8 + i][j6], acc6[i][j6]);
    __syncthreads();

    // softmax per row
    if (tid < 128) {
        int r = rowBase + tid;
        if (r < M) {
            float v[6];
            float m = -1e30f;
#pragma unroll
            for (int j = 0; j < 6; j++) {
                v[j] = rowacc[tid][j] + bd2[j];
                m = fmaxf(m, v[j]);
            }
            float ssum = 0.f;
#pragma unroll
            for (int j = 0; j < 6; j++) { v[j] = __expf(v[j] - m); ssum += v[j]; }
            float inv = 1.0f / ssum;
#pragma unroll
            for (int j = 0; j < 6; j++) out[(size_t)r * 6 + j] = v[j] * inv;
        }
    }
}

// ---------------- launch ----------------
static inline float* sym(const void* s) {
    void* p = nullptr;
    cudaGetSymbolAddress(&p, s);
    return (float*)p;
}

extern "C" void kernel_launch(void* const* d_in, const int* in_sizes, int n_in,
                              void* d_out, int out_size) {
    const float* x    = (const float*)d_in[0];
    const void*  ei   = d_in[1];
    const float* W1   = (const float*)d_in[2];
    const float* W2   = (const float*)d_in[4];
    const float* g1   = (const float*)d_in[6];
    const float* be1  = (const float*)d_in[7];
    const float* g2   = (const float*)d_in[8];
    const float* be2  = (const float*)d_in[9];
    const float* Wd1  = (const float*)d_in[10];
    const float* bd1  = (const float*)d_in[11];
    const float* Wd2  = (const float*)d_in[12];
    const float* bd2  = (const float*)d_in[13];
    float*       out  = (float*)d_out;

    float* xw1 = sym(g_xw1);
    float* h1  = sym(g_h1);
    float* xw2 = sym(g_xw2);
    float* h2  = sym(g_h2);

    // edge dtype detection + conversion to int32
    detect_k<<<1, 256>>>((const unsigned long long*)ei);
    cvt_edges_k<<<(N_EDGES + 255) / 256, 256>>>(ei);

    // degrees (shared by both conv layers)
    deg_init_k<<<(N_NODES + 255) / 256, 256>>>();
    deg_count_k<<<(N_EDGES + 255) / 256, 256>>>();
    dinv_k<<<(N_NODES + 255) / 256, 256>>>();

    // ---- layer 1: GCNConv(128->256) + BN + LeakyReLU (conv bias cancels in BN) ----
    {
        dim3 grid(256 / 128, (N_NODES + 127) / 128);
        sgemm128<true><<<grid, 256>>>(x, W1, xw1, h1, N_NODES, 256, 128);
    }
    aggregate_k<256><<<(int)(((size_t)N_EDGES * 32 + 255) / 256), 256>>>(xw1, h1);
    bn_zero_k<<<2, 256>>>(256);
    bn_reduce_k<256><<<512, 256>>>(h1);
    bn_scale_k<<<1, 256>>>(g1, be1, 256);
    bn_apply_k<256><<<(int)(((size_t)N_NODES * 256 + 255) / 256), 256>>>(h1);

    // ---- layer 2: GCNConv(256->512) + BN + LeakyReLU ----
    {
        dim3 grid(512 / 128, (N_NODES + 127) / 128);
        sgemm128<true><<<grid, 256>>>(h1, W2, xw2, h2, N_NODES, 512, 256);
    }
    aggregate_k<512><<<(int)(((size_t)N_EDGES * 32 + 255) / 256), 256>>>(xw2, h2);
    bn_zero_k<<<2, 256>>>(512);
    bn_reduce_k<512><<<512, 512>>>(h2);
    bn_scale_k<<<2, 256>>>(g2, be2, 512);
    bn_apply_k<512><<<(int)(((size_t)N_NODES * 512 + 255) / 256), 256>>>(h2);

    // ---- fused dense1 + LeakyReLU + dense2 + softmax ----
    dense_fused_k<<<(N_NODES + 127) / 128, 256>>>(h2, Wd1, bd1, Wd2, bd2, out, N_NODES);
}

// round 7
// speedup vs baseline: 1.1339x; 1.1339x over previous
#include <cuda_runtime.h>
#include <cuda_bf16.h>
#include <cstdint>

#define N_NODES 100000
#define N_EDGES 3200000
#define BN_EPS 1e-5f
#define SLOPE 0.01f
#define DK 1536   // 3 * 512 split-bf16 concatenated K

// ---------------- scratch (static device globals; no allocation) ----------------
// Arena aliasing: xw1 (dead after aggregate-1) and xw2 (dead after aggregate-2)
// live inside the a2 arena (written only after both are dead).
//   arena[0          : 102.4MB) = xw1   (float,  N*256)
//   arena[102.4MB    : 307.2MB) = xw2   (float,  N*512)
//   arena[0          : 307.2MB) = a2    (bf16,   N*1536)  -- after xw1/xw2 dead
__device__ unsigned char g_arena[(size_t)N_NODES * DK * 2];   // 307.2 MB
__device__ float g_deg[N_NODES];
__device__ float g_dinv[N_NODES];
__device__ int   g_src[N_EDGES];
__device__ int   g_dst[N_EDGES];
__device__ int   g_is64;
__device__ float g_h1 [(size_t)N_NODES * 256];   // 102.4 MB
__device__ float g_h2 [(size_t)N_NODES * 512];   // 204.8 MB
__device__ __nv_bfloat16 g_w2[(size_t)DK * 4096];      // 12.6 MB
__device__ float g_logits[(size_t)N_NODES * 6];        // 2.4 MB
__device__ float g_colsum[512];
__device__ float g_colsq [512];
__device__ float g_scale [512];
__device__ float g_shift [512];

// ---------------- edge dtype detection + conversion ----------------
__global__ void detect_k(const unsigned long long* __restrict__ p) {
    __shared__ int bad;
    if (threadIdx.x == 0) bad = 0;
    __syncthreads();
    for (int i = threadIdx.x; i < 4096; i += 256)
        if (p[i] >= (unsigned long long)N_NODES) bad = 1;
    __syncthreads();
    if (threadIdx.x == 0) g_is64 = bad ? 0 : 1;
}
__global__ void cvt_edges_k(const void* __restrict__ ei) {
    int e = blockIdx.x * blockDim.x + threadIdx.x;
    if (e >= N_EDGES) return;
    if (g_is64) {
        const long long* p = (const long long*)ei;
        g_src[e] = (int)p[e];
        g_dst[e] = (int)p[e + N_EDGES];
    } else {
        const int* p = (const int*)ei;
        g_src[e] = p[e];
        g_dst[e] = p[e + N_EDGES];
    }
}

// ---------------- degree / norm ----------------
__global__ void deg_init_k() {
    int i = blockIdx.x * blockDim.x + threadIdx.x;
    if (i < N_NODES) g_deg[i] = 1.0f;
}
__global__ void deg_count_k() {
    int e = blockIdx.x * blockDim.x + threadIdx.x;
    if (e < N_EDGES) atomicAdd(&g_deg[g_dst[e]], 1.0f);
}
__global__ void dinv_k() {
    int i = blockIdx.x * blockDim.x + threadIdx.x;
    if (i < N_NODES) {
        float d = g_deg[i];
        g_dinv[i] = d > 0.f ? rsqrtf(d) : 0.f;
    }
}

// ---------------- SGEMM (conv layers): C = A@B, + H = C*dinv^2 epilogue ----------------
template <bool SELFLOOP>
__global__ __launch_bounds__(256)
void sgemm128(const float* __restrict__ A, const float* __restrict__ B,
              float* __restrict__ C, float* __restrict__ H,
              int M, int Nn, int K) {
    __shared__ float As[8][128];
    __shared__ float Bs[8][128];
    const int tid = threadIdx.x;
    const int blockRow = blockIdx.y, blockCol = blockIdx.x;
    const int tRow = tid / 16, tCol = tid % 16;
    const int aRow = tid / 2, aCol = (tid % 2) * 4;
    const int bRow = tid / 32, bCol = (tid % 32) * 4;
    const int rowBase = blockRow * 128;

    float acc[8][8];
#pragma unroll
    for (int i = 0; i < 8; i++)
#pragma unroll
        for (int j = 0; j < 8; j++) acc[i][j] = 0.f;

    for (int k0 = 0; k0 < K; k0 += 8) {
        int gr = rowBase + aRow;
        float4 a = make_float4(0.f, 0.f, 0.f, 0.f);
        if (gr < M) a = *reinterpret_cast<const float4*>(&A[(size_t)gr * K + k0 + aCol]);
        As[aCol + 0][aRow] = a.x;
        As[aCol + 1][aRow] = a.y;
        As[aCol + 2][aRow] = a.z;
        As[aCol + 3][aRow] = a.w;
        float4 b = *reinterpret_cast<const float4*>(
            &B[(size_t)(k0 + bRow) * Nn + blockCol * 128 + bCol]);
        *reinterpret_cast<float4*>(&Bs[bRow][bCol]) = b;
        __syncthreads();
#pragma unroll
        for (int k = 0; k < 8; k++) {
            float rm[8], rn[8];
            *(float4*)&rm[0] = *(float4*)&As[k][tRow * 8];
            *(float4*)&rm[4] = *(float4*)&As[k][tRow * 8 + 4];
            *(float4*)&rn[0] = *(float4*)&Bs[k][tCol * 8];
            *(float4*)&rn[4] = *(float4*)&Bs[k][tCol * 8 + 4];
#pragma unroll
            for (int i = 0; i < 8; i++)
#pragma unroll
                for (int j = 0; j < 8; j++) acc[i][j] += rm[i] * rn[j];
        }
        __syncthreads();
    }

    const int colBase = blockCol * 128 + tCol * 8;
#pragma unroll
    for (int i = 0; i < 8; i++) {
        int r = rowBase + tRow * 8 + i;
        if (r < M) {
            *reinterpret_cast<float4*>(&C[(size_t)r * Nn + colBase])     = *(float4*)&acc[i][0];
            *reinterpret_cast<float4*>(&C[(size_t)r * Nn + colBase + 4]) = *(float4*)&acc[i][4];
            if (SELFLOOP) {
                float di = g_dinv[r];
                float s = di * di;
                float v[8];
#pragma unroll
                for (int j = 0; j < 8; j++) v[j] = acc[i][j] * s;
                *reinterpret_cast<float4*>(&H[(size_t)r * Nn + colBase])     = *(float4*)&v[0];
                *reinterpret_cast<float4*>(&H[(size_t)r * Nn + colBase + 4]) = *(float4*)&v[4];
            }
        }
    }
}

// ---------------- edge aggregation ----------------
template <int C>
__global__ __launch_bounds__(256)
void aggregate_k(const float* __restrict__ xw, float* __restrict__ h) {
    int warp = (blockIdx.x * blockDim.x + threadIdx.x) >> 5;
    int lane = threadIdx.x & 31;
    if (warp >= N_EDGES) return;
    int s = g_src[warp];
    int d = g_dst[warp];
    float nrm = g_dinv[s] * g_dinv[d];
    const float4* xr = reinterpret_cast<const float4*>(xw + (size_t)s * C);
    float* hr = h + (size_t)d * C;
#pragma unroll
    for (int c = lane; c < C / 4; c += 32) {
        float4 v = xr[c];
        atomicAdd(&hr[c * 4 + 0], v.x * nrm);
        atomicAdd(&hr[c * 4 + 1], v.y * nrm);
        atomicAdd(&hr[c * 4 + 2], v.z * nrm);
        atomicAdd(&hr[c * 4 + 3], v.w * nrm);
    }
}

// ---------------- BatchNorm ----------------
__global__ void bn_zero_k(int C) {
    int c = threadIdx.x + blockIdx.x * blockDim.x;
    if (c < C) { g_colsum[c] = 0.f; g_colsq[c] = 0.f; }
}
template <int C>
__global__ void bn_reduce_k(const float* __restrict__ h) {
    int c = threadIdx.x;
    int rows_per = (N_NODES + gridDim.x - 1) / gridDim.x;
    int r0 = blockIdx.x * rows_per;
    int r1 = min(r0 + rows_per, N_NODES);
    float s = 0.f, sq = 0.f;
    for (int r = r0; r < r1; r++) {
        float v = h[(size_t)r * C + c];
        s += v; sq += v * v;
    }
    atomicAdd(&g_colsum[c], s);
    atomicAdd(&g_colsq[c], sq);
}
__global__ void bn_scale_k(const float* __restrict__ g, const float* __restrict__ be, int C) {
    int c = threadIdx.x + blockIdx.x * blockDim.x;
    if (c < C) {
        float mean = g_colsum[c] * (1.0f / N_NODES);
        float var  = g_colsq[c] * (1.0f / N_NODES) - mean * mean;
        float a = g[c] * rsqrtf(var + BN_EPS);
        g_scale[c] = a;
        g_shift[c] = be[c] - mean * a;
    }
}
template <int C>
__global__ void bn_apply_k(float* __restrict__ h) {
    size_t idx = (size_t)blockIdx.x * blockDim.x + threadIdx.x;
    if (idx < (size_t)N_NODES * C) {
        int c = (int)(idx & (C - 1));
        float v = h[idx] * g_scale[c] + g_shift[c];
        h[idx] = v >= 0.f ? v : SLOPE * v;
    }
}

// ---------------- split-bf16 precompute ----------------
// a2[m, 0:512]=hi, [512:1024]=hi, [1024:1536]=lo   (A' = [hi | hi | lo])
__global__ void split_a_k(const float* __restrict__ h2, __nv_bfloat16* __restrict__ a2) {
    size_t idx = (size_t)blockIdx.x * blockDim.x + threadIdx.x;
    if (idx >= (size_t)N_NODES * 512) return;
    int m = (int)(idx >> 9), k = (int)(idx & 511);
    float v = h2[idx];
    __nv_bfloat16 hi = __float2bfloat16(v);
    __nv_bfloat16 lo = __float2bfloat16(v - __bfloat162float(hi));
    size_t base = (size_t)m * DK;
    a2[base + k]        = hi;
    a2[base + 512 + k]  = hi;
    a2[base + 1024 + k] = lo;
}
// w2 rows: [k]=hi, [512+k]=lo, [1024+k]=hi   (W' = [hi ; lo ; hi])
__global__ void split_w_k(const float* __restrict__ Wd1) {
    size_t idx = (size_t)blockIdx.x * blockDim.x + threadIdx.x;
    if (idx >= (size_t)512 * 4096) return;
    int k = (int)(idx >> 12), n = (int)(idx & 4095);
    float v = Wd1[idx];
    __nv_bfloat16 hi = __float2bfloat16(v);
    __nv_bfloat16 lo = __float2bfloat16(v - __bfloat162float(hi));
    g_w2[(size_t)k * 4096 + n]          = hi;
    g_w2[(size_t)(512 + k) * 4096 + n]  = lo;
    g_w2[(size_t)(1024 + k) * 4096 + n] = hi;
}

__global__ void logits_init_k(const float* __restrict__ bd2) {
    size_t idx = (size_t)blockIdx.x * blockDim.x + threadIdx.x;
    if (idx < (size_t)N_NODES * 6)
        g_logits[idx] = bd2[idx % 6];
}

// ---------------- dense1(bf16 tensor core) + LeakyReLU + Wd2 contraction ----------------
// grid (32 n-blocks, 782 m-blocks); block 512 thr = 16 warps (4m x 4n), warp tile 32x32.
__global__ __launch_bounds__(512, 1)
void dense_bf16_k(const __nv_bfloat16* __restrict__ A2,
                  const __nv_bfloat16* __restrict__ W2b,
                  const float* __restrict__ bd1,
                  const float* __restrict__ Wd2,
                  float* __restrict__ logits, int M) {
    __shared__ __nv_bfloat16 As[128][36];   // [m][k]
    __shared__ __nv_bfloat16 Bs[128][36];   // [n][k]
    __shared__ float W2s[128][6];
    __shared__ float b1s[128];
    __shared__ float rowacc[128][6];

    const int tid  = threadIdx.x;
    const int warp = tid >> 5, lane = tid & 31;
    const int g = lane >> 2, tig = lane & 3;
    const int wm = (warp >> 2) * 32, wn = (warp & 3) * 32;
    const int rowBase = blockIdx.y * 128;
    const int n0 = blockIdx.x * 128;

    for (int i = tid; i < 768; i += 512) {
        W2s[i / 6][i % 6] = Wd2[(size_t)(n0 + i / 6) * 6 + (i % 6)];
        ((float*)rowacc)[i] = 0.f;
    }
    for (int i = tid; i < 128; i += 512) b1s[i] = bd1[n0 + i];

    float acc[2][4][4];
#pragma unroll
    for (int s = 0; s < 2; s++)
#pragma unroll
        for (int j = 0; j < 4; j++)
#pragma unroll
            for (int c = 0; c < 4; c++) acc[s][j][c] = 0.f;

    for (int k0 = 0; k0 < DK; k0 += 32) {
        // A tile: 128x32, b32 (2 bf16) per thread x 4 reps
#pragma unroll
        for (int rep = 0; rep < 4; rep++) {
            int idx = rep * 1024 + tid * 2;
            int m = idx >> 5, k = idx & 31;
            uint32_t v = 0;
            if (rowBase + m < M)
                v = *reinterpret_cast<const uint32_t*>(&A2[(size_t)(rowBase + m) * DK + k0 + k]);
            *reinterpret_cast<uint32_t*>(&As[m][k]) = v;
        }
        // B tile: Bs[n][k] = W2b[(k0+k)*4096 + n0+n], n fastest for coalescing
#pragma unroll
        for (int rep = 0; rep < 8; rep++) {
            int idx = rep * 512 + tid;
            int k = idx >> 7, n = idx & 127;
            Bs[n][k] = W2b[(size_t)(k0 + k) * 4096 + n0 + n];
        }
        __syncthreads();

#pragma unroll
        for (int kk = 0; kk < 32; kk += 16) {
            uint32_t a[2][4], b[4][2];
#pragma unroll
            for (int s = 0; s < 2; s++) {
                a[s][0] = *reinterpret_cast<uint32_t*>(&As[wm + s * 16 + g][kk + tig * 2]);
                a[s][1] = *reinterpret_cast<uint32_t*>(&As[wm + s * 16 + 8 + g][kk + tig * 2]);
                a[s][2] = *reinterpret_cast<uint32_t*>(&As[wm + s * 16 + g][kk + 8 + tig * 2]);
                a[s][3] = *reinterpret_cast<uint32_t*>(&As[wm + s * 16 + 8 + g][kk + 8 + tig * 2]);
            }
#pragma unroll
            for (int j = 0; j < 4; j++) {
                b[j][0] = *reinterpret_cast<uint32_t*>(&Bs[wn + j * 8 + g][kk + tig * 2]);
                b[j][1] = *reinterpret_cast<uint32_t*>(&Bs[wn + j * 8 + g][kk + 8 + tig * 2]);
            }
#pragma unroll
            for (int s = 0; s < 2; s++)
#pragma unroll
                for (int j = 0; j < 4; j++)
                    asm volatile(
                        "mma.sync.aligned.m16n8k16.row.col.f32.bf16.bf16.f32 "
                        "{%0,%1,%2,%3}, {%4,%5,%6,%7}, {%8,%9}, {%0,%1,%2,%3};"
                        : "+f"(acc[s][j][0]), "+f"(acc[s][j][1]),
                          "+f"(acc[s][j][2]), "+f"(acc[s][j][3])
                        : "r"(a[s][0]), "r"(a[s][1]), "r"(a[s][2]), "r"(a[s][3]),
                          "r"(b[j][0]), "r"(b[j][1]));
        }
        __syncthreads();
    }

    // epilogue: bias + leaky + Wd2 contraction -> per-thread row partials
    float acc6[4][6];
#pragma unroll
    for (int r = 0; r < 4; r++)
#pragma unroll
        for (int c = 0; c < 6; c++) acc6[r][c] = 0.f;

#pragma unroll
    for (int s = 0; s < 2; s++)
#pragma unroll
        for (int j = 0; j < 4; j++) {
            int col = wn + j * 8 + 2 * tig;
            float b0 = b1s[col], b1 = b1s[col + 1];
            float t;
            t = acc[s][j][0] + b0; t = t >= 0.f ? t : SLOPE * t;
#pragma unroll
            for (int c = 0; c < 6; c++) acc6[s * 2 + 0][c] += t * W2s[col][c];
            t = acc[s][j][1] + b1; t = t >= 0.f ? t : SLOPE * t;
#pragma unroll
            for (int c = 0; c < 6; c++) acc6[s * 2 + 0][c] += t * W2s[col + 1][c];
            t = acc[s][j][2] + b0; t = t >= 0.f ? t : SLOPE * t;
#pragma unroll
            for (int c = 0; c < 6; c++) acc6[s * 2 + 1][c] += t * W2s[col][c];
            t = acc[s][j][3] + b1; t = t >= 0.f ? t : SLOPE * t;
#pragma unroll
            for (int c = 0; c < 6; c++) acc6[s * 2 + 1][c] += t * W2s[col + 1][c];
        }

#pragma unroll
    for (int s = 0; s < 2; s++) {
        int r0 = wm + s * 16 + g;
        int r1 = wm + s * 16 + 8 + g;
#pragma unroll
        for (int c = 0; c < 6; c++) {
            atomicAdd(&rowacc[r0][c], acc6[s * 2 + 0][c]);
            atomicAdd(&rowacc[r1][c], acc6[s * 2 + 1][c]);
        }
    }
    __syncthreads();

    for (int i = tid; i < 768; i += 512) {
        int r = i / 6, c = i % 6;
        if (rowBase + r < M)
            atomicAdd(&logits[(size_t)(rowBase + r) * 6 + c], rowacc[r][c]);
    }
}

// ---------------- softmax ----------------
__global__ void softmax_k(const float* __restrict__ logits, float* __restrict__ out) {
    int r = blockIdx.x * blockDim.x + threadIdx.x;
    if (r >= N_NODES) return;
    float v[6];
    float m = -1e30f;
#pragma unroll
    for (int j = 0; j < 6; j++) { v[j] = logits[(size_t)r * 6 + j]; m = fmaxf(m, v[j]); }
    float ssum = 0.f;
#pragma unroll
    for (int j = 0; j < 6; j++) { v[j] = __expf(v[j] - m); ssum += v[j]; }
    float inv = 1.0f / ssum;
#pragma unroll
    for (int j = 0; j < 6; j++) out[(size_t)r * 6 + j] = v[j] * inv;
}

// ---------------- launch ----------------
static inline void* symp(const void* s) {
    void* p = nullptr;
    cudaGetSymbolAddress(&p, s);
    return p;
}

extern "C" void kernel_launch(void* const* d_in, const int* in_sizes, int n_in,
                              void* d_out, int out_size) {
    const float* x    = (const float*)d_in[0];
    const void*  ei   = d_in[1];
    const float* W1   = (const float*)d_in[2];
    const float* W2   = (const float*)d_in[4];
    const float* g1   = (const float*)d_in[6];
    const float* be1  = (const float*)d_in[7];
    const float* g2   = (const float*)d_in[8];
    const float* be2  = (const float*)d_in[9];
    const float* Wd1  = (const float*)d_in[10];
    const float* bd1  = (const float*)d_in[11];
    const float* Wd2  = (const float*)d_in[12];
    const float* bd2  = (const float*)d_in[13];
    float*       out  = (float*)d_out;

    unsigned char* arena = (unsigned char*)symp(g_arena);
    float* xw1 = (float*)arena;                                   // [0, 102.4MB)
    float* xw2 = (float*)(arena + (size_t)N_NODES * 256 * 4);     // [102.4, 307.2MB)
    __nv_bfloat16* a2 = (__nv_bfloat16*)arena;                    // full arena (after xw dead)
    float* h1  = (float*)symp(g_h1);
    float* h2  = (float*)symp(g_h2);
    float* lg  = (float*)symp(g_logits);
    __nv_bfloat16* w2 = (__nv_bfloat16*)symp(g_w2);

    detect_k<<<1, 256>>>((const unsigned long long*)ei);
    cvt_edges_k<<<(N_EDGES + 255) / 256, 256>>>(ei);

    deg_init_k<<<(N_NODES + 255) / 256, 256>>>();
    deg_count_k<<<(N_EDGES + 255) / 256, 256>>>();
    dinv_k<<<(N_NODES + 255) / 256, 256>>>();

    // Wd1 split can start early (independent)
    split_w_k<<<(int)(((size_t)512 * 4096 + 255) / 256), 256>>>(Wd1);
    logits_init_k<<<(N_NODES * 6 + 255) / 256, 256>>>(bd2);

    // ---- layer 1 ----
    {
        dim3 grid(256 / 128, (N_NODES + 127) / 128);
        sgemm128<true><<<grid, 256>>>(x, W1, xw1, h1, N_NODES, 256, 128);
    }
    aggregate_k<256><<<(int)(((size_t)N_EDGES * 32 + 255) / 256), 256>>>(xw1, h1);
    bn_zero_k<<<2, 256>>>(256);
    bn_reduce_k<256><<<512, 256>>>(h1);
    bn_scale_k<<<1, 256>>>(g1, be1, 256);
    bn_apply_k<256><<<(int)(((size_t)N_NODES * 256 + 255) / 256), 256>>>(h1);

    // ---- layer 2 ----
    {
        dim3 grid(512 / 128, (N_NODES + 127) / 128);
        sgemm128<true><<<grid, 256>>>(h1, W2, xw2, h2, N_NODES, 512, 256);
    }
    aggregate_k<512><<<(int)(((size_t)N_EDGES * 32 + 255) / 256), 256>>>(xw2, h2);
    bn_zero_k<<<2, 256>>>(512);
    bn_reduce_k<512><<<512, 512>>>(h2);
    bn_scale_k<<<2, 256>>>(g2, be2, 512);
    bn_apply_k<512><<<(int)(((size_t)N_NODES * 512 + 255) / 256), 256>>>(h2);

    // ---- split h2 -> bf16 hi/hi/lo (xw1/xw2 dead; arena reused as a2) ----
    split_a_k<<<(int)(((size_t)N_NODES * 512 + 255) / 256), 256>>>(h2, a2);

    // ---- dense1 (tensor core) + LeakyReLU + dense2 partial sums ----
    {
        dim3 grid(4096 / 128, (N_NODES + 127) / 128);
        dense_bf16_k<<<grid, 512>>>(a2, w2, bd1, Wd2, lg, N_NODES);
    }

    // ---- softmax ----
    softmax_k<<<(N_NODES + 255) / 256, 256>>>(lg, out);
}

// round 8
// speedup vs baseline: 1.5755x; 1.3895x over previous
#include <cuda_runtime.h>
#include <cuda_bf16.h>
#include <cstdint>

#define N_NODES 100000
#define N_EDGES 3200000
#define BN_EPS 1e-5f
#define SLOPE 0.01f
#define DK 1536           // 3 * 512 split-bf16 concatenated K
#define SCAN_CHUNK 512
#define SCAN_NB ((N_NODES + SCAN_CHUNK - 1) / SCAN_CHUNK)   // 196

// ---------------- scratch (static device globals; no allocation) ----------------
// Arena aliasing: xw1 (dead after gather-1) and xw2 (dead after gather-2)
// live inside the a2 arena (a2 written only after both are dead).
__device__ unsigned char g_arena[(size_t)N_NODES * DK * 2];   // 307.2 MB
__device__ float g_dinv[N_NODES];
__device__ int   g_cnt [N_NODES];
__device__ int   g_fill[N_NODES];
__device__ int   g_rowptr[N_NODES];
__device__ int   g_blocksums[SCAN_NB];
__device__ int   g_src[N_EDGES];
__device__ int   g_dst[N_EDGES];
__device__ int   g_csrc[N_EDGES];                // CSR column (src) ids, 12.8 MB
__device__ int   g_is64;
__device__ float g_h1 [(size_t)N_NODES * 256];   // 102.4 MB
__device__ float g_h2 [(size_t)N_NODES * 512];   // 204.8 MB
__device__ __nv_bfloat16 g_w2[(size_t)DK * 4096];// 12.6 MB
__device__ float g_logits[(size_t)N_NODES * 6];  // 2.4 MB
__device__ float g_colsum[512];
__device__ float g_colsq [512];
__device__ float g_scale [512];
__device__ float g_shift [512];

// ---------------- edge dtype detection + conversion ----------------
__global__ void detect_k(const unsigned long long* __restrict__ p) {
    __shared__ int bad;
    if (threadIdx.x == 0) bad = 0;
    __syncthreads();
    for (int i = threadIdx.x; i < 4096; i += 256)
        if (p[i] >= (unsigned long long)N_NODES) bad = 1;
    __syncthreads();
    if (threadIdx.x == 0) g_is64 = bad ? 0 : 1;
}
__global__ void cvt_edges_k(const void* __restrict__ ei) {
    int e = blockIdx.x * blockDim.x + threadIdx.x;
    if (e >= N_EDGES) return;
    if (g_is64) {
        const long long* p = (const long long*)ei;
        g_src[e] = (int)p[e];
        g_dst[e] = (int)p[e + N_EDGES];
    } else {
        const int* p = (const int*)ei;
        g_src[e] = p[e];
        g_dst[e] = p[e + N_EDGES];
    }
}

// ---------------- degree / norm / CSR build ----------------
__global__ void cnt_zero_k() {
    int i = blockIdx.x * blockDim.x + threadIdx.x;
    if (i < N_NODES) { g_cnt[i] = 0; g_fill[i] = 0; }
}
__global__ void deg_count_k() {
    int e = blockIdx.x * blockDim.x + threadIdx.x;
    if (e < N_EDGES) atomicAdd(&g_cnt[g_dst[e]], 1);
}
__global__ void dinv_k() {
    int i = blockIdx.x * blockDim.x + threadIdx.x;
    if (i < N_NODES) g_dinv[i] = rsqrtf((float)(g_cnt[i] + 1));  // +1 self-loop
}
// scan step 1: per-chunk sums
__global__ void scan1_k() {
    __shared__ int sh[SCAN_CHUNK];
    int base = blockIdx.x * SCAN_CHUNK;
    int i = base + threadIdx.x;
    sh[threadIdx.x] = (i < N_NODES) ? g_cnt[i] : 0;
    __syncthreads();
    for (int off = SCAN_CHUNK / 2; off > 0; off >>= 1) {
        if (threadIdx.x < off) sh[threadIdx.x] += sh[threadIdx.x + off];
        __syncthreads();
    }
    if (threadIdx.x == 0) g_blocksums[blockIdx.x] = sh[0];
}
// scan step 2: sequential exclusive scan of 196 chunk sums (trivial cost)
__global__ void scan2_k() {
    if (threadIdx.x == 0) {
        int run = 0;
        for (int b = 0; b < SCAN_NB; b++) {
            int v = g_blocksums[b];
            g_blocksums[b] = run;
            run += v;
        }
    }
}
// scan step 3: per-chunk exclusive scan + chunk offset -> rowptr
__global__ void scan3_k() {
    __shared__ int sh[SCAN_CHUNK];
    int base = blockIdx.x * SCAN_CHUNK;
    int i = base + threadIdx.x;
    int v = (i < N_NODES) ? g_cnt[i] : 0;
    sh[threadIdx.x] = v;
    __syncthreads();
    // Hillis-Steele inclusive scan
    for (int off = 1; off < SCAN_CHUNK; off <<= 1) {
        int t = (threadIdx.x >= off) ? sh[threadIdx.x - off] : 0;
        __syncthreads();
        sh[threadIdx.x] += t;
        __syncthreads();
    }
    if (i < N_NODES)
        g_rowptr[i] = g_blocksums[blockIdx.x] + sh[threadIdx.x] - v;  // exclusive
}
__global__ void scatter_k() {
    int e = blockIdx.x * blockDim.x + threadIdx.x;
    if (e >= N_EDGES) return;
    int d = g_dst[e];
    int pos = g_rowptr[d] + atomicAdd(&g_fill[d], 1);
    g_csrc[pos] = g_src[e];
}

// ---------------- SGEMM (conv layers): C = A@B ----------------
__global__ __launch_bounds__(256)
void sgemm128(const float* __restrict__ A, const float* __restrict__ B,
              float* __restrict__ C, int M, int Nn, int K) {
    __shared__ float As[8][128];
    __shared__ float Bs[8][128];
    const int tid = threadIdx.x;
    const int blockRow = blockIdx.y, blockCol = blockIdx.x;
    const int tRow = tid / 16, tCol = tid % 16;
    const int aRow = tid / 2, aCol = (tid % 2) * 4;
    const int bRow = tid / 32, bCol = (tid % 32) * 4;
    const int rowBase = blockRow * 128;

    float acc[8][8];
#pragma unroll
    for (int i = 0; i < 8; i++)
#pragma unroll
        for (int j = 0; j < 8; j++) acc[i][j] = 0.f;

    for (int k0 = 0; k0 < K; k0 += 8) {
        int gr = rowBase + aRow;
        float4 a = make_float4(0.f, 0.f, 0.f, 0.f);
        if (gr < M) a = *reinterpret_cast<const float4*>(&A[(size_t)gr * K + k0 + aCol]);
        As[aCol + 0][aRow] = a.x;
        As[aCol + 1][aRow] = a.y;
        As[aCol + 2][aRow] = a.z;
        As[aCol + 3][aRow] = a.w;
        float4 b = *reinterpret_cast<const float4*>(
            &B[(size_t)(k0 + bRow) * Nn + blockCol * 128 + bCol]);
        *reinterpret_cast<float4*>(&Bs[bRow][bCol]) = b;
        __syncthreads();
#pragma unroll
        for (int k = 0; k < 8; k++) {
            float rm[8], rn[8];
            *(float4*)&rm[0] = *(float4*)&As[k][tRow * 8];
            *(float4*)&rm[4] = *(float4*)&As[k][tRow * 8 + 4];
            *(float4*)&rn[0] = *(float4*)&Bs[k][tCol * 8];
            *(float4*)&rn[4] = *(float4*)&Bs[k][tCol * 8 + 4];
#pragma unroll
            for (int i = 0; i < 8; i++)
#pragma unroll
                for (int j = 0; j < 8; j++) acc[i][j] += rm[i] * rn[j];
        }
        __syncthreads();
    }

    const int colBase = blockCol * 128 + tCol * 8;
#pragma unroll
    for (int i = 0; i < 8; i++) {
        int r = rowBase + tRow * 8 + i;
        if (r < M) {
            *reinterpret_cast<float4*>(&C[(size_t)r * Nn + colBase])     = *(float4*)&acc[i][0];
            *reinterpret_cast<float4*>(&C[(size_t)r * Nn + colBase + 4]) = *(float4*)&acc[i][4];
        }
    }
}

// ---------------- CSR gather aggregation (no atomics) ----------------
// warp per dst node: h[d] = xw[d]*dinv[d]^2 + sum_s xw[s]*dinv[s]*dinv[d]
template <int C>
__global__ __launch_bounds__(256)
void gather_k(const float* __restrict__ xw, float* __restrict__ h) {
    constexpr int V = C / 128;   // float4 per lane (C=256 -> 2, C=512 -> 4)
    int d = (blockIdx.x * blockDim.x + threadIdx.x) >> 5;
    int lane = threadIdx.x & 31;
    if (d >= N_NODES) return;
    float dd = g_dinv[d];

    float4 acc[V];
    {
        float sl = dd * dd;
        const float4* self = reinterpret_cast<const float4*>(xw + (size_t)d * C);
#pragma unroll
        for (int v = 0; v < V; v++) {
            float4 t = self[lane + v * 32];
            acc[v].x = t.x * sl; acc[v].y = t.y * sl;
            acc[v].z = t.z * sl; acc[v].w = t.w * sl;
        }
    }
    int start = g_rowptr[d];
    int cnt = g_cnt[d];
    for (int j = 0; j < cnt; j++) {
        int s = g_csrc[start + j];
        float nrm = g_dinv[s] * dd;
        const float4* xr = reinterpret_cast<const float4*>(xw + (size_t)s * C);
#pragma unroll
        for (int v = 0; v < V; v++) {
            float4 t = xr[lane + v * 32];
            acc[v].x += t.x * nrm; acc[v].y += t.y * nrm;
            acc[v].z += t.z * nrm; acc[v].w += t.w * nrm;
        }
    }
    float4* hr = reinterpret_cast<float4*>(h + (size_t)d * C);
#pragma unroll
    for (int v = 0; v < V; v++) hr[lane + v * 32] = acc[v];
}

// ---------------- BatchNorm ----------------
__global__ void bn_zero_k(int C) {
    int c = threadIdx.x + blockIdx.x * blockDim.x;
    if (c < C) { g_colsum[c] = 0.f; g_colsq[c] = 0.f; }
}
template <int C>
__global__ void bn_reduce_k(const float* __restrict__ h) {
    int c = threadIdx.x;
    int rows_per = (N_NODES + gridDim.x - 1) / gridDim.x;
    int r0 = blockIdx.x * rows_per;
    int r1 = min(r0 + rows_per, N_NODES);
    float s = 0.f, sq = 0.f;
    for (int r = r0; r < r1; r++) {
        float v = h[(size_t)r * C + c];
        s += v; sq += v * v;
    }
    atomicAdd(&g_colsum[c], s);
    atomicAdd(&g_colsq[c], sq);
}
__global__ void bn_scale_k(const float* __restrict__ g, const float* __restrict__ be, int C) {
    int c = threadIdx.x + blockIdx.x * blockDim.x;
    if (c < C) {
        float mean = g_colsum[c] * (1.0f / N_NODES);
        float var  = g_colsq[c] * (1.0f / N_NODES) - mean * mean;
        float a = g[c] * rsqrtf(var + BN_EPS);
        g_scale[c] = a;
        g_shift[c] = be[c] - mean * a;
    }
}
template <int C>
__global__ void bn_apply_k(float* __restrict__ h) {
    size_t idx = (size_t)blockIdx.x * blockDim.x + threadIdx.x;
    if (idx < (size_t)N_NODES * C) {
        int c = (int)(idx & (C - 1));
        float v = h[idx] * g_scale[c] + g_shift[c];
        h[idx] = v >= 0.f ? v : SLOPE * v;
    }
}

// ---------------- split-bf16 precompute ----------------
__global__ void split_a_k(const float* __restrict__ h2, __nv_bfloat16* __restrict__ a2) {
    size_t idx = (size_t)blockIdx.x * blockDim.x + threadIdx.x;
    if (idx >= (size_t)N_NODES * 512) return;
    int m = (int)(idx >> 9), k = (int)(idx & 511);
    float v = h2[idx];
    __nv_bfloat16 hi = __float2bfloat16(v);
    __nv_bfloat16 lo = __float2bfloat16(v - __bfloat162float(hi));
    size_t base = (size_t)m * DK;
    a2[base + k]        = hi;
    a2[base + 512 + k]  = hi;
    a2[base + 1024 + k] = lo;
}
__global__ void split_w_k(const float* __restrict__ Wd1) {
    size_t idx = (size_t)blockIdx.x * blockDim.x + threadIdx.x;
    if (idx >= (size_t)512 * 4096) return;
    int k = (int)(idx >> 12), n = (int)(idx & 4095);
    float v = Wd1[idx];
    __nv_bfloat16 hi = __float2bfloat16(v);
    __nv_bfloat16 lo = __float2bfloat16(v - __bfloat162float(hi));
    g_w2[(size_t)k * 4096 + n]          = hi;
    g_w2[(size_t)(512 + k) * 4096 + n]  = lo;
    g_w2[(size_t)(1024 + k) * 4096 + n] = hi;
}
__global__ void logits_init_k(const float* __restrict__ bd2) {
    size_t idx = (size_t)blockIdx.x * blockDim.x + threadIdx.x;
    if (idx < (size_t)N_NODES * 6)
        g_logits[idx] = bd2[idx % 6];
}

// ---------------- dense1(bf16 mma) + LeakyReLU + Wd2 contraction ----------------
__global__ __launch_bounds__(512, 1)
void dense_bf16_k(const __nv_bfloat16* __restrict__ A2,
                  const __nv_bfloat16* __restrict__ W2b,
                  const float* __restrict__ bd1,
                  const float* __restrict__ Wd2,
                  float* __restrict__ logits, int M) {
    __shared__ __nv_bfloat16 As[128][36];
    __shared__ __nv_bfloat16 Bs[128][36];
    __shared__ float W2s[128][6];
    __shared__ float b1s[128];
    __shared__ float rowacc[128][6];

    const int tid  = threadIdx.x;
    const int warp = tid >> 5, lane = tid & 31;
    const int g = lane >> 2, tig = lane & 3;
    const int wm = (warp >> 2) * 32, wn = (warp & 3) * 32;
    const int rowBase = blockIdx.y * 128;
    const int n0 = blockIdx.x * 128;

    for (int i = tid; i < 768; i += 512) {
        W2s[i / 6][i % 6] = Wd2[(size_t)(n0 + i / 6) * 6 + (i % 6)];
        ((float*)rowacc)[i] = 0.f;
    }
    for (int i = tid; i < 128; i += 512) b1s[i] = bd1[n0 + i];

    float acc[2][4][4];
#pragma unroll
    for (int s = 0; s < 2; s++)
#pragma unroll
        for (int j = 0; j < 4; j++)
#pragma unroll
            for (int c = 0; c < 4; c++) acc[s][j][c] = 0.f;

    for (int k0 = 0; k0 < DK; k0 += 32) {
#pragma unroll
        for (int rep = 0; rep < 4; rep++) {
            int idx = rep * 1024 + tid * 2;
            int m = idx >> 5, k = idx & 31;
            uint32_t v = 0;
            if (rowBase + m < M)
                v = *reinterpret_cast<const uint32_t*>(&A2[(size_t)(rowBase + m) * DK + k0 + k]);
            *reinterpret_cast<uint32_t*>(&As[m][k]) = v;
        }
#pragma unroll
        for (int rep = 0; rep < 8; rep++) {
            int idx = rep * 512 + tid;
            int k = idx >> 7, n = idx & 127;
            Bs[n][k] = W2b[(size_t)(k0 + k) * 4096 + n0 + n];
        }
        __syncthreads();

#pragma unroll
        for (int kk = 0; kk < 32; kk += 16) {
            uint32_t a[2][4], b[4][2];
#pragma unroll
            for (int s = 0; s < 2; s++) {
                a[s][0] = *reinterpret_cast<uint32_t*>(&As[wm + s * 16 + g][kk + tig * 2]);
                a[s][1] = *reinterpret_cast<uint32_t*>(&As[wm + s * 16 + 8 + g][kk + tig * 2]);
                a[s][2] = *reinterpret_cast<uint32_t*>(&As[wm + s * 16 + g][kk + 8 + tig * 2]);
                a[s][3] = *reinterpret_cast<uint32_t*>(&As[wm + s * 16 + 8 + g][kk + 8 + tig * 2]);
            }
#pragma unroll
            for (int j = 0; j < 4; j++) {
                b[j][0] = *reinterpret_cast<uint32_t*>(&Bs[wn + j * 8 + g][kk + tig * 2]);
                b[j][1] = *reinterpret_cast<uint32_t*>(&Bs[wn + j * 8 + g][kk + 8 + tig * 2]);
            }
#pragma unroll
            for (int s = 0; s < 2; s++)
#pragma unroll
                for (int j = 0; j < 4; j++)
                    asm volatile(
                        "mma.sync.aligned.m16n8k16.row.col.f32.bf16.bf16.f32 "
                        "{%0,%1,%2,%3}, {%4,%5,%6,%7}, {%8,%9}, {%0,%1,%2,%3};"
                        : "+f"(acc[s][j][0]), "+f"(acc[s][j][1]),
                          "+f"(acc[s][j][2]), "+f"(acc[s][j][3])
                        : "r"(a[s][0]), "r"(a[s][1]), "r"(a[s][2]), "r"(a[s][3]),
                          "r"(b[j][0]), "r"(b[j][1]));
        }
        __syncthreads();
    }

    float acc6[4][6];
#pragma unroll
    for (int r = 0; r < 4; r++)
#pragma unroll
        for (int c = 0; c < 6; c++) acc6[r][c] = 0.f;

#pragma unroll
    for (int s = 0; s < 2; s++)
#pragma unroll
        for (int j = 0; j < 4; j++) {
            int col = wn + j * 8 + 2 * tig;
            float b0 = b1s[col], b1 = b1s[col + 1];
            float t;
            t = acc[s][j][0] + b0; t = t >= 0.f ? t : SLOPE * t;
#pragma unroll
            for (int c = 0; c < 6; c++) acc6[s * 2 + 0][c] += t * W2s[col][c];
            t = acc[s][j][1] + b1; t = t >= 0.f ? t : SLOPE * t;
#pragma unroll
            for (int c = 0; c < 6; c++) acc6[s * 2 + 0][c] += t * W2s[col + 1][c];
            t = acc[s][j][2] + b0; t = t >= 0.f ? t : SLOPE * t;
#pragma unroll
            for (int c = 0; c < 6; c++) acc6[s * 2 + 1][c] += t * W2s[col][c];
            t = acc[s][j][3] + b1; t = t >= 0.f ? t : SLOPE * t;
#pragma unroll
            for (int c = 0; c < 6; c++) acc6[s * 2 + 1][c] += t * W2s[col + 1][c];
        }

#pragma unroll
    for (int s = 0; s < 2; s++) {
        int r0 = wm + s * 16 + g;
        int r1 = wm + s * 16 + 8 + g;
#pragma unroll
        for (int c = 0; c < 6; c++) {
            atomicAdd(&rowacc[r0][c], acc6[s * 2 + 0][c]);
            atomicAdd(&rowacc[r1][c], acc6[s * 2 + 1][c]);
        }
    }
    __syncthreads();

    for (int i = tid; i < 768; i += 512) {
        int r = i / 6, c = i % 6;
        if (rowBase + r < M)
            atomicAdd(&logits[(size_t)(rowBase + r) * 6 + c], rowacc[r][c]);
    }
}

// ---------------- softmax ----------------
__global__ void softmax_k(const float* __restrict__ logits, float* __restrict__ out) {
    int r = blockIdx.x * blockDim.x + threadIdx.x;
    if (r >= N_NODES) return;
    float v[6];
    float m = -1e30f;
#pragma unroll
    for (int j = 0; j < 6; j++) { v[j] = logits[(size_t)r * 6 + j]; m = fmaxf(m, v[j]); }
    float ssum = 0.f;
#pragma unroll
    for (int j = 0; j < 6; j++) { v[j] = __expf(v[j] - m); ssum += v[j]; }
    float inv = 1.0f / ssum;
#pragma unroll
    for (int j = 0; j < 6; j++) out[(size_t)r * 6 + j] = v[j] * inv;
}

// ---------------- launch ----------------
static inline void* symp(const void* s) {
    void* p = nullptr;
    cudaGetSymbolAddress(&p, s);
    return p;
}

extern "C" void kernel_launch(void* const* d_in, const int* in_sizes, int n_in,
                              void* d_out, int out_size) {
    const float* x    = (const float*)d_in[0];
    const void*  ei   = d_in[1];
    const float* W1   = (const float*)d_in[2];
    const float* W2   = (const float*)d_in[4];
    const float* g1   = (const float*)d_in[6];
    const float* be1  = (const float*)d_in[7];
    const float* g2   = (const float*)d_in[8];
    const float* be2  = (const float*)d_in[9];
    const float* Wd1  = (const float*)d_in[10];
    const float* bd1  = (const float*)d_in[11];
    const float* Wd2  = (const float*)d_in[12];
    const float* bd2  = (const float*)d_in[13];
    float*       out  = (float*)d_out;

    unsigned char* arena = (unsigned char*)symp(g_arena);
    float* xw1 = (float*)arena;
    float* xw2 = (float*)(arena + (size_t)N_NODES * 256 * 4);
    __nv_bfloat16* a2 = (__nv_bfloat16*)arena;
    float* h1  = (float*)symp(g_h1);
    float* h2  = (float*)symp(g_h2);
    float* lg  = (float*)symp(g_logits);
    __nv_bfloat16* w2 = (__nv_bfloat16*)symp(g_w2);

    // edge conversion + CSR build
    detect_k<<<1, 256>>>((const unsigned long long*)ei);
    cvt_edges_k<<<(N_EDGES + 255) / 256, 256>>>(ei);
    cnt_zero_k<<<(N_NODES + 255) / 256, 256>>>();
    deg_count_k<<<(N_EDGES + 255) / 256, 256>>>();
    dinv_k<<<(N_NODES + 255) / 256, 256>>>();
    scan1_k<<<SCAN_NB, SCAN_CHUNK>>>();
    scan2_k<<<1, 32>>>();
    scan3_k<<<SCAN_NB, SCAN_CHUNK>>>();
    scatter_k<<<(N_EDGES + 255) / 256, 256>>>();

    // independent weight prep
    split_w_k<<<(int)(((size_t)512 * 4096 + 255) / 256), 256>>>(Wd1);
    logits_init_k<<<(N_NODES * 6 + 255) / 256, 256>>>(bd2);

    // ---- layer 1: GCNConv(128->256) + BN + LeakyReLU ----
    {
        dim3 grid(256 / 128, (N_NODES + 127) / 128);
        sgemm128<<<grid, 256>>>(x, W1, xw1, N_NODES, 256, 128);
    }
    gather_k<256><<<(int)(((size_t)N_NODES * 32 + 255) / 256), 256>>>(xw1, h1);
    bn_zero_k<<<2, 256>>>(256);
    bn_reduce_k<256><<<512, 256>>>(h1);
    bn_scale_k<<<1, 256>>>(g1, be1, 256);
    bn_apply_k<256><<<(int)(((size_t)N_NODES * 256 + 255) / 256), 256>>>(h1);

    // ---- layer 2: GCNConv(256->512) + BN + LeakyReLU ----
    {
        dim3 grid(512 / 128, (N_NODES + 127) / 128);
        sgemm128<<<grid, 256>>>(h1, W2, xw2, N_NODES, 512, 256);
    }
    gather_k<512><<<(int)(((size_t)N_NODES * 32 + 255) / 256), 256>>>(xw2, h2);
    bn_zero_k<<<2, 256>>>(512);
    bn_reduce_k<512><<<512, 512>>>(h2);
    bn_scale_k<<<2, 256>>>(g2, be2, 512);
    bn_apply_k<512><<<(int)(((size_t)N_NODES * 512 + 255) / 256), 256>>>(h2);

    // ---- split h2 -> bf16 hi/hi/lo (xw1/xw2 dead; arena reused as a2) ----
    split_a_k<<<(int)(((size_t)N_NODES * 512 + 255) / 256), 256>>>(h2, a2);

    // ---- dense1 (tensor core) + LeakyReLU + dense2 partial sums ----
    {
        dim3 grid(4096 / 128, (N_NODES + 127) / 128);
        dense_bf16_k<<<grid, 512>>>(a2, w2, bd1, Wd2, lg, N_NODES);
    }

    // ---- softmax ----
    softmax_k<<<(N_NODES + 255) / 256, 256>>>(lg, out);
}

// round 9
// speedup vs baseline: 1.6333x; 1.0367x over previous
#include <cuda_runtime.h>
#include <cuda_bf16.h>
#include <cstdint>

#define N_NODES 100000
#define N_EDGES 3200000
#define BN_EPS 1e-5f
#define SLOPE 0.01f
#define DK 1536           // dense: 3 * 512 split-bf16 concatenated K
#define SCAN_CHUNK 512
#define SCAN_NB ((N_NODES + SCAN_CHUNK - 1) / SCAN_CHUNK)   // 196

// ---------------- scratch (static device globals; no allocation) ----------------
// Arena aliasing (lifetimes disjoint):
//   ga1 = arena[0      : 76.8MB)   bf16 N*384   (gathered x, split)   dead after GEMM1
//   ga2 = arena[76.8MB : 230.4MB)  bf16 N*768   (gathered h1, split)  dead after GEMM2
//   a2  = arena[0      : 307.2MB)  bf16 N*1536  (split h2 for dense)
__device__ unsigned char g_arena[(size_t)N_NODES * DK * 2];   // 307.2 MB
__device__ float g_dinv[N_NODES];
__device__ int   g_cnt [N_NODES];
__device__ int   g_fill[N_NODES];
__device__ int   g_rowptr[N_NODES];
__device__ int   g_blocksums[SCAN_NB];
__device__ int   g_src[N_EDGES];
__device__ int   g_dst[N_EDGES];
__device__ int   g_csrc[N_EDGES];
__device__ int   g_is64;
__device__ float g_h1 [(size_t)N_NODES * 256];     // 102.4 MB
__device__ float g_h2 [(size_t)N_NODES * 512];     // 204.8 MB
__device__ __nv_bfloat16 g_w2 [(size_t)DK * 4096]; // dense Wd1 split, 12.6 MB
__device__ __nv_bfloat16 g_w1s[(size_t)384 * 256]; // conv W1 split
__device__ __nv_bfloat16 g_w2s[(size_t)768 * 512]; // conv W2 split
__device__ float g_logits[(size_t)N_NODES * 6];
__device__ float g_colsum[512];
__device__ float g_colsq [512];
__device__ float g_scale [512];
__device__ float g_shift [512];

// ---------------- edge dtype detection + conversion ----------------
__global__ void detect_k(const unsigned long long* __restrict__ p) {
    __shared__ int bad;
    if (threadIdx.x == 0) bad = 0;
    __syncthreads();
    for (int i = threadIdx.x; i < 4096; i += 256)
        if (p[i] >= (unsigned long long)N_NODES) bad = 1;
    __syncthreads();
    if (threadIdx.x == 0) g_is64 = bad ? 0 : 1;
}
__global__ void cvt_edges_k(const void* __restrict__ ei) {
    int e = blockIdx.x * blockDim.x + threadIdx.x;
    if (e >= N_EDGES) return;
    if (g_is64) {
        const long long* p = (const long long*)ei;
        g_src[e] = (int)p[e];
        g_dst[e] = (int)p[e + N_EDGES];
    } else {
        const int* p = (const int*)ei;
        g_src[e] = p[e];
        g_dst[e] = p[e + N_EDGES];
    }
}

// ---------------- degree / norm / CSR build ----------------
__global__ void cnt_zero_k() {
    int i = blockIdx.x * blockDim.x + threadIdx.x;
    if (i < N_NODES) { g_cnt[i] = 0; g_fill[i] = 0; }
}
__global__ void deg_count_k() {
    int e = blockIdx.x * blockDim.x + threadIdx.x;
    if (e < N_EDGES) atomicAdd(&g_cnt[g_dst[e]], 1);
}
__global__ void dinv_k() {
    int i = blockIdx.x * blockDim.x + threadIdx.x;
    if (i < N_NODES) g_dinv[i] = rsqrtf((float)(g_cnt[i] + 1));
}
__global__ void scan1_k() {
    __shared__ int sh[SCAN_CHUNK];
    int i = blockIdx.x * SCAN_CHUNK + threadIdx.x;
    sh[threadIdx.x] = (i < N_NODES) ? g_cnt[i] : 0;
    __syncthreads();
    for (int off = SCAN_CHUNK / 2; off > 0; off >>= 1) {
        if (threadIdx.x < off) sh[threadIdx.x] += sh[threadIdx.x + off];
        __syncthreads();
    }
    if (threadIdx.x == 0) g_blocksums[blockIdx.x] = sh[0];
}
__global__ void scan2_k() {
    if (threadIdx.x == 0) {
        int run = 0;
        for (int b = 0; b < SCAN_NB; b++) {
            int v = g_blocksums[b];
            g_blocksums[b] = run;
            run += v;
        }
    }
}
__global__ void scan3_k() {
    __shared__ int sh[SCAN_CHUNK];
    int i = blockIdx.x * SCAN_CHUNK + threadIdx.x;
    int v = (i < N_NODES) ? g_cnt[i] : 0;
    sh[threadIdx.x] = v;
    __syncthreads();
    for (int off = 1; off < SCAN_CHUNK; off <<= 1) {
        int t = (threadIdx.x >= off) ? sh[threadIdx.x - off] : 0;
        __syncthreads();
        sh[threadIdx.x] += t;
        __syncthreads();
    }
    if (i < N_NODES)
        g_rowptr[i] = g_blocksums[blockIdx.x] + sh[threadIdx.x] - v;
}
__global__ void scatter_k() {
    int e = blockIdx.x * blockDim.x + threadIdx.x;
    if (e >= N_EDGES) return;
    int d = g_dst[e];
    int pos = g_rowptr[d] + atomicAdd(&g_fill[d], 1);
    g_csrc[pos] = g_src[e];
}

// ---------------- gather + split-bf16 epilogue ----------------
// warp per dst node; out row layout: [hi(C) | hi(C) | lo(C)], row stride 3C.
template <int C>
__global__ __launch_bounds__(256)
void gather_split_k(const float* __restrict__ xin, __nv_bfloat16* __restrict__ aout) {
    constexpr int V = C / 128;
    int d = (blockIdx.x * blockDim.x + threadIdx.x) >> 5;
    int lane = threadIdx.x & 31;
    if (d >= N_NODES) return;
    float dd = g_dinv[d];

    float4 acc[V];
    {
        float sl = dd * dd;
        const float4* self = reinterpret_cast<const float4*>(xin + (size_t)d * C);
#pragma unroll
        for (int v = 0; v < V; v++) {
            float4 t = self[lane + v * 32];
            acc[v].x = t.x * sl; acc[v].y = t.y * sl;
            acc[v].z = t.z * sl; acc[v].w = t.w * sl;
        }
    }
    int start = g_rowptr[d];
    int cnt = g_cnt[d];
    for (int j = 0; j < cnt; j++) {
        int s = g_csrc[start + j];
        float nrm = g_dinv[s] * dd;
        const float4* xr = reinterpret_cast<const float4*>(xin + (size_t)s * C);
#pragma unroll
        for (int v = 0; v < V; v++) {
            float4 t = xr[lane + v * 32];
            acc[v].x += t.x * nrm; acc[v].y += t.y * nrm;
            acc[v].z += t.z * nrm; acc[v].w += t.w * nrm;
        }
    }
    size_t base = (size_t)d * (3 * C);
#pragma unroll
    for (int v = 0; v < V; v++) {
        int col = (lane + v * 32) * 4;
        float vals[4] = {acc[v].x, acc[v].y, acc[v].z, acc[v].w};
        __nv_bfloat16 hi[4];
        __nv_bfloat16 lo[4];
#pragma unroll
        for (int t = 0; t < 4; t++) {
            hi[t] = __float2bfloat16(vals[t]);
            lo[t] = __float2bfloat16(vals[t] - __bfloat162float(hi[t]));
        }
        __nv_bfloat162 h01 = __halves2bfloat162(hi[0], hi[1]);
        __nv_bfloat162 h23 = __halves2bfloat162(hi[2], hi[3]);
        __nv_bfloat162 l01 = __halves2bfloat162(lo[0], lo[1]);
        __nv_bfloat162 l23 = __halves2bfloat162(lo[2], lo[3]);
        *reinterpret_cast<__nv_bfloat162*>(&aout[base + col])             = h01;
        *reinterpret_cast<__nv_bfloat162*>(&aout[base + col + 2])         = h23;
        *reinterpret_cast<__nv_bfloat162*>(&aout[base + C + col])         = h01;
        *reinterpret_cast<__nv_bfloat162*>(&aout[base + C + col + 2])     = h23;
        *reinterpret_cast<__nv_bfloat162*>(&aout[base + 2 * C + col])     = l01;
        *reinterpret_cast<__nv_bfloat162*>(&aout[base + 2 * C + col + 2]) = l23;
    }
}

// ---------------- weight splits ----------------
// out rows: [k]=hi, [K+k]=lo, [2K+k]=hi  (W' = [hi ; lo ; hi])
__global__ void split_w_generic_k(const float* __restrict__ W, __nv_bfloat16* __restrict__ out,
                                  int K, int Nn) {
    int idx = blockIdx.x * blockDim.x + threadIdx.x;
    if (idx >= K * Nn) return;
    int k = idx / Nn, n = idx % Nn;
    float v = W[idx];
    __nv_bfloat16 hi = __float2bfloat16(v);
    __nv_bfloat16 lo = __float2bfloat16(v - __bfloat162float(hi));
    out[(size_t)k * Nn + n]           = hi;
    out[(size_t)(K + k) * Nn + n]     = lo;
    out[(size_t)(2 * K + k) * Nn + n] = hi;
}
__global__ void logits_init_k(const float* __restrict__ bd2) {
    size_t idx = (size_t)blockIdx.x * blockDim.x + threadIdx.x;
    if (idx < (size_t)N_NODES * 6)
        g_logits[idx] = bd2[idx % 6];
}

// ---------------- generic split-bf16 GEMM: C[M,Nn] = A2[M,DKt] @ Wb[DKt,Nn] ----------------
// block tile 128x128, 16 warps (4m x 4n), warp tile 32x32; fp32 output.
__global__ __launch_bounds__(512, 1)
void gemm_bf16_k(const __nv_bfloat16* __restrict__ A2,
                 const __nv_bfloat16* __restrict__ Wb,
                 float* __restrict__ C, int M, int Nn, int DKt) {
    __shared__ __nv_bfloat16 As[128][36];
    __shared__ __nv_bfloat16 Bs[128][36];
    const int tid  = threadIdx.x;
    const int warp = tid >> 5, lane = tid & 31;
    const int g = lane >> 2, tig = lane & 3;
    const int wm = (warp >> 2) * 32, wn = (warp & 3) * 32;
    const int rowBase = blockIdx.y * 128;
    const int n0 = blockIdx.x * 128;

    float acc[2][4][4];
#pragma unroll
    for (int s = 0; s < 2; s++)
#pragma unroll
        for (int j = 0; j < 4; j++)
#pragma unroll
            for (int c = 0; c < 4; c++) acc[s][j][c] = 0.f;

    for (int k0 = 0; k0 < DKt; k0 += 32) {
#pragma unroll
        for (int rep = 0; rep < 4; rep++) {
            int idx = rep * 1024 + tid * 2;
            int m = idx >> 5, k = idx & 31;
            uint32_t v = 0;
            if (rowBase + m < M)
                v = *reinterpret_cast<const uint32_t*>(&A2[(size_t)(rowBase + m) * DKt + k0 + k]);
            *reinterpret_cast<uint32_t*>(&As[m][k]) = v;
        }
#pragma unroll
        for (int rep = 0; rep < 8; rep++) {
            int idx = rep * 512 + tid;
            int k = idx >> 7, n = idx & 127;
            Bs[n][k] = Wb[(size_t)(k0 + k) * Nn + n0 + n];
        }
        __syncthreads();

#pragma unroll
        for (int kk = 0; kk < 32; kk += 16) {
            uint32_t a[2][4], b[4][2];
#pragma unroll
            for (int s = 0; s < 2; s++) {
                a[s][0] = *reinterpret_cast<uint32_t*>(&As[wm + s * 16 + g][kk + tig * 2]);
                a[s][1] = *reinterpret_cast<uint32_t*>(&As[wm + s * 16 + 8 + g][kk + tig * 2]);
                a[s][2] = *reinterpret_cast<uint32_t*>(&As[wm + s * 16 + g][kk + 8 + tig * 2]);
                a[s][3] = *reinterpret_cast<uint32_t*>(&As[wm + s * 16 + 8 + g][kk + 8 + tig * 2]);
            }
#pragma unroll
            for (int j = 0; j < 4; j++) {
                b[j][0] = *reinterpret_cast<uint32_t*>(&Bs[wn + j * 8 + g][kk + tig * 2]);
                b[j][1] = *reinterpret_cast<uint32_t*>(&Bs[wn + j * 8 + g][kk + 8 + tig * 2]);
            }
#pragma unroll
            for (int s = 0; s < 2; s++)
#pragma unroll
                for (int j = 0; j < 4; j++)
                    asm volatile(
                        "mma.sync.aligned.m16n8k16.row.col.f32.bf16.bf16.f32 "
                        "{%0,%1,%2,%3}, {%4,%5,%6,%7}, {%8,%9}, {%0,%1,%2,%3};"
                        : "+f"(acc[s][j][0]), "+f"(acc[s][j][1]),
                          "+f"(acc[s][j][2]), "+f"(acc[s][j][3])
                        : "r"(a[s][0]), "r"(a[s][1]), "r"(a[s][2]), "r"(a[s][3]),
                          "r"(b[j][0]), "r"(b[j][1]));
        }
        __syncthreads();
    }

#pragma unroll
    for (int s = 0; s < 2; s++) {
        int r0 = rowBase + wm + s * 16 + g;
        int r1 = r0 + 8;
#pragma unroll
        for (int j = 0; j < 4; j++) {
            int col = n0 + wn + j * 8 + 2 * tig;
            if (r0 < M) {
                C[(size_t)r0 * Nn + col]     = acc[s][j][0];
                C[(size_t)r0 * Nn + col + 1] = acc[s][j][1];
            }
            if (r1 < M) {
                C[(size_t)r1 * Nn + col]     = acc[s][j][2];
                C[(size_t)r1 * Nn + col + 1] = acc[s][j][3];
            }
        }
    }
}

// ---------------- BatchNorm ----------------
__global__ void bn_zero_k(int C) {
    int c = threadIdx.x + blockIdx.x * blockDim.x;
    if (c < C) { g_colsum[c] = 0.f; g_colsq[c] = 0.f; }
}
template <int C>
__global__ void bn_reduce_k(const float* __restrict__ h) {
    int c = threadIdx.x;
    int rows_per = (N_NODES + gridDim.x - 1) / gridDim.x;
    int r0 = blockIdx.x * rows_per;
    int r1 = min(r0 + rows_per, N_NODES);
    float s = 0.f, sq = 0.f;
    for (int r = r0; r < r1; r++) {
        float v = h[(size_t)r * C + c];
        s += v; sq += v * v;
    }
    atomicAdd(&g_colsum[c], s);
    atomicAdd(&g_colsq[c], sq);
}
__global__ void bn_scale_k(const float* __restrict__ g, const float* __restrict__ be, int C) {
    int c = threadIdx.x + blockIdx.x * blockDim.x;
    if (c < C) {
        float mean = g_colsum[c] * (1.0f / N_NODES);
        float var  = g_colsq[c] * (1.0f / N_NODES) - mean * mean;
        float a = g[c] * rsqrtf(var + BN_EPS);
        g_scale[c] = a;
        g_shift[c] = be[c] - mean * a;
    }
}
template <int C>
__global__ void bn_apply_k(float* __restrict__ h) {
    size_t idx = (size_t)blockIdx.x * blockDim.x + threadIdx.x;
    if (idx < (size_t)N_NODES * C) {
        int c = (int)(idx & (C - 1));
        float v = h[idx] * g_scale[c] + g_shift[c];
        h[idx] = v >= 0.f ? v : SLOPE * v;
    }
}

// ---------------- fused BN-apply + leaky + split (h2raw -> a2 for dense) ----------------
__global__ void split_a_fused_k(const float* __restrict__ h2raw, __nv_bfloat16* __restrict__ a2) {
    size_t idx = (size_t)blockIdx.x * blockDim.x + threadIdx.x;
    if (idx >= (size_t)N_NODES * 512) return;
    int m = (int)(idx >> 9), k = (int)(idx & 511);
    float v = h2raw[idx] * g_scale[k] + g_shift[k];
    v = v >= 0.f ? v : SLOPE * v;
    __nv_bfloat16 hi = __float2bfloat16(v);
    __nv_bfloat16 lo = __float2bfloat16(v - __bfloat162float(hi));
    size_t base = (size_t)m * DK;
    a2[base + k]        = hi;
    a2[base + 512 + k]  = hi;
    a2[base + 1024 + k] = lo;
}

// ---------------- dense1(bf16 mma) + LeakyReLU + Wd2 contraction ----------------
__global__ __launch_bounds__(512, 1)
void dense_bf16_k(const __nv_bfloat16* __restrict__ A2,
                  const __nv_bfloat16* __restrict__ W2b,
                  const float* __restrict__ bd1,
                  const float* __restrict__ Wd2,
                  float* __restrict__ logits, int M) {
    __shared__ __nv_bfloat16 As[128][36];
    __shared__ __nv_bfloat16 Bs[128][36];
    __shared__ float W2s[128][6];
    __shared__ float b1s[128];
    __shared__ float rowacc[128][6];

    const int tid  = threadIdx.x;
    const int warp = tid >> 5, lane = tid & 31;
    const int g = lane >> 2, tig = lane & 3;
    const int wm = (warp >> 2) * 32, wn = (warp & 3) * 32;
    const int rowBase = blockIdx.y * 128;
    const int n0 = blockIdx.x * 128;

    for (int i = tid; i < 768; i += 512) {
        W2s[i / 6][i % 6] = Wd2[(size_t)(n0 + i / 6) * 6 + (i % 6)];
        ((float*)rowacc)[i] = 0.f;
    }
    for (int i = tid; i < 128; i += 512) b1s[i] = bd1[n0 + i];

    float acc[2][4][4];
#pragma unroll
    for (int s = 0; s < 2; s++)
#pragma unroll
        for (int j = 0; j < 4; j++)
#pragma unroll
            for (int c = 0; c < 4; c++) acc[s][j][c] = 0.f;

    for (int k0 = 0; k0 < DK; k0 += 32) {
#pragma unroll
        for (int rep = 0; rep < 4; rep++) {
            int idx = rep * 1024 + tid * 2;
            int m = idx >> 5, k = idx & 31;
            uint32_t v = 0;
            if (rowBase + m < M)
                v = *reinterpret_cast<const uint32_t*>(&A2[(size_t)(rowBase + m) * DK + k0 + k]);
            *reinterpret_cast<uint32_t*>(&As[m][k]) = v;
        }
#pragma unroll
        for (int rep = 0; rep < 8; rep++) {
            int idx = rep * 512 + tid;
            int k = idx >> 7, n = idx & 127;
            Bs[n][k] = W2b[(size_t)(k0 + k) * 4096 + n0 + n];
        }
        __syncthreads();

#pragma unroll
        for (int kk = 0; kk < 32; kk += 16) {
            uint32_t a[2][4], b[4][2];
#pragma unroll
            for (int s = 0; s < 2; s++) {
                a[s][0] = *reinterpret_cast<uint32_t*>(&As[wm + s * 16 + g][kk + tig * 2]);
                a[s][1] = *reinterpret_cast<uint32_t*>(&As[wm + s * 16 + 8 + g][kk + tig * 2]);
                a[s][2] = *reinterpret_cast<uint32_t*>(&As[wm + s * 16 + g][kk + 8 + tig * 2]);
                a[s][3] = *reinterpret_cast<uint32_t*>(&As[wm + s * 16 + 8 + g][kk + 8 + tig * 2]);
            }
#pragma unroll
            for (int j = 0; j < 4; j++) {
                b[j][0] = *reinterpret_cast<uint32_t*>(&Bs[wn + j * 8 + g][kk + tig * 2]);
                b[j][1] = *reinterpret_cast<uint32_t*>(&Bs[wn + j * 8 + g][kk + 8 + tig * 2]);
            }
#pragma unroll
            for (int s = 0; s < 2; s++)
#pragma unroll
                for (int j = 0; j < 4; j++)
                    asm volatile(
                        "mma.sync.aligned.m16n8k16.row.col.f32.bf16.bf16.f32 "
                        "{%0,%1,%2,%3}, {%4,%5,%6,%7}, {%8,%9}, {%0,%1,%2,%3};"
                        : "+f"(acc[s][j][0]), "+f"(acc[s][j][1]),
                          "+f"(acc[s][j][2]), "+f"(acc[s][j][3])
                        : "r"(a[s][0]), "r"(a[s][1]), "r"(a[s][2]), "r"(a[s][3]),
                          "r"(b[j][0]), "r"(b[j][1]));
        }
        __syncthreads();
    }

    float acc6[4][6];
#pragma unroll
    for (int r = 0; r < 4; r++)
#pragma unroll
        for (int c = 0; c < 6; c++) acc6[r][c] = 0.f;

#pragma unroll
    for (int s = 0; s < 2; s++)
#pragma unroll
        for (int j = 0; j < 4; j++) {
            int col = wn + j * 8 + 2 * tig;
            float b0 = b1s[col], b1 = b1s[col + 1];
            float t;
            t = acc[s][j][0] + b0; t = t >= 0.f ? t : SLOPE * t;
#pragma unroll
            for (int c = 0; c < 6; c++) acc6[s * 2 + 0][c] += t * W2s[col][c];
            t = acc[s][j][1] + b1; t = t >= 0.f ? t : SLOPE * t;
#pragma unroll
            for (int c = 0; c < 6; c++) acc6[s * 2 + 0][c] += t * W2s[col + 1][c];
            t = acc[s][j][2] + b0; t = t >= 0.f ? t : SLOPE * t;
#pragma unroll
            for (int c = 0; c < 6; c++) acc6[s * 2 + 1][c] += t * W2s[col][c];
            t = acc[s][j][3] + b1; t = t >= 0.f ? t : SLOPE * t;
#pragma unroll
            for (int c = 0; c < 6; c++) acc6[s * 2 + 1][c] += t * W2s[col + 1][c];
        }

#pragma unroll
    for (int s = 0; s < 2; s++) {
        int r0 = wm + s * 16 + g;
        int r1 = wm + s * 16 + 8 + g;
#pragma unroll
        for (int c = 0; c < 6; c++) {
            atomicAdd(&rowacc[r0][c], acc6[s * 2 + 0][c]);
            atomicAdd(&rowacc[r1][c], acc6[s * 2 + 1][c]);
        }
    }
    __syncthreads();

    for (int i = tid; i < 768; i += 512) {
        int r = i / 6, c = i % 6;
        if (rowBase + r < M)
            atomicAdd(&logits[(size_t)(rowBase + r) * 6 + c], rowacc[r][c]);
    }
}

// ---------------- softmax ----------------
__global__ void softmax_k(const float* __restrict__ logits, float* __restrict__ out) {
    int r = blockIdx.x * blockDim.x + threadIdx.x;
    if (r >= N_NODES) return;
    float v[6];
    float m = -1e30f;
#pragma unroll
    for (int j = 0; j < 6; j++) { v[j] = logits[(size_t)r * 6 + j]; m = fmaxf(m, v[j]); }
    float ssum = 0.f;
#pragma unroll
    for (int j = 0; j < 6; j++) { v[j] = __expf(v[j] - m); ssum += v[j]; }
    float inv = 1.0f / ssum;
#pragma unroll
    for (int j = 0; j < 6; j++) out[(size_t)r * 6 + j] = v[j] * inv;
}

// ---------------- launch ----------------
static inline void* symp(const void* s) {
    void* p = nullptr;
    cudaGetSymbolAddress(&p, s);
    return p;
}

extern "C" void kernel_launch(void* const* d_in, const int* in_sizes, int n_in,
                              void* d_out, int out_size) {
    const float* x    = (const float*)d_in[0];
    const void*  ei   = d_in[1];
    const float* W1   = (const float*)d_in[2];
    const float* W2   = (const float*)d_in[4];
    const float* g1   = (const float*)d_in[6];
    const float* be1  = (const float*)d_in[7];
    const float* g2   = (const float*)d_in[8];
    const float* be2  = (const float*)d_in[9];
    const float* Wd1  = (const float*)d_in[10];
    const float* bd1  = (const float*)d_in[11];
    const float* Wd2  = (const float*)d_in[12];
    const float* bd2  = (const float*)d_in[13];
    float*       out  = (float*)d_out;

    unsigned char* arena = (unsigned char*)symp(g_arena);
    __nv_bfloat16* ga1 = (__nv_bfloat16*)arena;                                   // N*384
    __nv_bfloat16* ga2 = (__nv_bfloat16*)(arena + (size_t)N_NODES * 384 * 2);     // N*768
    __nv_bfloat16* a2  = (__nv_bfloat16*)arena;                                   // N*1536
    float* h1  = (float*)symp(g_h1);
    float* h2  = (float*)symp(g_h2);
    float* lg  = (float*)symp(g_logits);
    __nv_bfloat16* w2d = (__nv_bfloat16*)symp(g_w2);
    __nv_bfloat16* w1s = (__nv_bfloat16*)symp(g_w1s);
    __nv_bfloat16* w2s = (__nv_bfloat16*)symp(g_w2s);

    // edge conversion + CSR build
    detect_k<<<1, 256>>>((const unsigned long long*)ei);
    cvt_edges_k<<<(N_EDGES + 255) / 256, 256>>>(ei);
    cnt_zero_k<<<(N_NODES + 255) / 256, 256>>>();
    deg_count_k<<<(N_EDGES + 255) / 256, 256>>>();
    dinv_k<<<(N_NODES + 255) / 256, 256>>>();
    scan1_k<<<SCAN_NB, SCAN_CHUNK>>>();
    scan2_k<<<1, 32>>>();
    scan3_k<<<SCAN_NB, SCAN_CHUNK>>>();
    scatter_k<<<(N_EDGES + 255) / 256, 256>>>();

    // weight prep (independent)
    split_w_generic_k<<<(int)(((size_t)512 * 4096 + 255) / 256), 256>>>(Wd1, w2d, 512, 4096);
    split_w_generic_k<<<(128 * 256 + 255) / 256, 256>>>(W1, w1s, 128, 256);
    split_w_generic_k<<<(256 * 512 + 255) / 256, 256>>>(W2, w2s, 256, 512);
    logits_init_k<<<(N_NODES * 6 + 255) / 256, 256>>>(bd2);

    // ---- layer 1: gather(x) -> GEMM -> BN + LeakyReLU ----
    gather_split_k<128><<<(int)(((size_t)N_NODES * 32 + 255) / 256), 256>>>(x, ga1);
    {
        dim3 grid(256 / 128, (N_NODES + 127) / 128);
        gemm_bf16_k<<<grid, 512>>>(ga1, w1s, h1, N_NODES, 256, 384);
    }
    bn_zero_k<<<2, 256>>>(256);
    bn_reduce_k<256><<<512, 256>>>(h1);
    bn_scale_k<<<1, 256>>>(g1, be1, 256);
    bn_apply_k<256><<<(int)(((size_t)N_NODES * 256 + 255) / 256), 256>>>(h1);

    // ---- layer 2: gather(h1) -> GEMM -> BN stats (apply fused into split) ----
    gather_split_k<256><<<(int)(((size_t)N_NODES * 32 + 255) / 256), 256>>>(h1, ga2);
    {
        dim3 grid(512 / 128, (N_NODES + 127) / 128);
        gemm_bf16_k<<<grid, 512>>>(ga2, w2s, h2, N_NODES, 512, 768);
    }
    bn_zero_k<<<2, 256>>>(512);
    bn_reduce_k<512><<<512, 512>>>(h2);
    bn_scale_k<<<2, 256>>>(g2, be2, 512);

    // ---- fused BN-apply + leaky + split (h2raw -> a2) ----
    split_a_fused_k<<<(int)(((size_t)N_NODES * 512 + 255) / 256), 256>>>(h2, a2);

    // ---- dense1 (tensor core) + LeakyReLU + dense2 partial sums ----
    {
        dim3 grid(4096 / 128, (N_NODES + 127) / 128);
        dense_bf16_k<<<grid, 512>>>(a2, w2d, bd1, Wd2, lg, N_NODES);
    }

    // ---- softmax ----
    softmax_k<<<(N_NODES + 255) / 256, 256>>>(lg, out);
}

// round 10
// speedup vs baseline: 3.3499x; 2.0510x over previous
#include <cuda_runtime.h>
#include <cuda_bf16.h>
#include <cstdint>

#define N_NODES 100000
#define N_EDGES 3200000
#define BN_EPS 1e-5f
#define SLOPE 0.01f
#define DK 1536
#define SCAN_CHUNK 512
#define SCAN_NB ((N_NODES + SCAN_CHUNK - 1) / SCAN_CHUNK)

// ---------------- scratch (static device globals; no allocation) ----------------
__device__ unsigned char g_arena[(size_t)N_NODES * DK * 2];   // 307.2 MB
__device__ float g_dinv[N_NODES];
__device__ int   g_cnt [N_NODES];
__device__ int   g_fill[N_NODES];
__device__ int   g_rowptr[N_NODES];
__device__ int   g_blocksums[SCAN_NB];
__device__ int   g_src[N_EDGES];
__device__ int   g_dst[N_EDGES];
__device__ int   g_csrc[N_EDGES];
__device__ int   g_is64;
__device__ float g_h1 [(size_t)N_NODES * 256];
__device__ float g_h2 [(size_t)N_NODES * 512];
__device__ __nv_bfloat16 g_wd [(size_t)4096 * DK];  // dense Wd1 split, TRANSPOSED [n][3K]
__device__ __nv_bfloat16 g_w1s[(size_t)256 * 384];  // conv W1 split, transposed
__device__ __nv_bfloat16 g_w2s[(size_t)512 * 768];  // conv W2 split, transposed
__device__ float g_logits[(size_t)N_NODES * 6];
__device__ float g_colsum[512];
__device__ float g_colsq [512];
__device__ float g_scale [512];
__device__ float g_shift [512];

// ---------------- cp.async helpers ----------------
__device__ __forceinline__ void cpa16(uint32_t dst, const void* src, int srcsize) {
    asm volatile("cp.async.cg.shared.global [%0], [%1], 16, %2;"
                 :: "r"(dst), "l"(src), "r"(srcsize));
}
__device__ __forceinline__ void cpa_commit() {
    asm volatile("cp.async.commit_group;");
}
template <int N>
__device__ __forceinline__ void cpa_wait() {
    asm volatile("cp.async.wait_group %0;" :: "n"(N));
}

// ---------------- edge dtype detection + conversion ----------------
__global__ void detect_k(const unsigned long long* __restrict__ p) {
    __shared__ int bad;
    if (threadIdx.x == 0) bad = 0;
    __syncthreads();
    for (int i = threadIdx.x; i < 4096; i += 256)
        if (p[i] >= (unsigned long long)N_NODES) bad = 1;
    __syncthreads();
    if (threadIdx.x == 0) g_is64 = bad ? 0 : 1;
}
__global__ void cvt_edges_k(const void* __restrict__ ei) {
    int e = blockIdx.x * blockDim.x + threadIdx.x;
    if (e >= N_EDGES) return;
    if (g_is64) {
        const long long* p = (const long long*)ei;
        g_src[e] = (int)p[e];
        g_dst[e] = (int)p[e + N_EDGES];
    } else {
        const int* p = (const int*)ei;
        g_src[e] = p[e];
        g_dst[e] = p[e + N_EDGES];
    }
}

// ---------------- degree / norm / CSR build ----------------
__global__ void cnt_zero_k() {
    int i = blockIdx.x * blockDim.x + threadIdx.x;
    if (i < N_NODES) { g_cnt[i] = 0; g_fill[i] = 0; }
}
__global__ void deg_count_k() {
    int e = blockIdx.x * blockDim.x + threadIdx.x;
    if (e < N_EDGES) atomicAdd(&g_cnt[g_dst[e]], 1);
}
__global__ void dinv_k() {
    int i = blockIdx.x * blockDim.x + threadIdx.x;
    if (i < N_NODES) g_dinv[i] = rsqrtf((float)(g_cnt[i] + 1));
}
__global__ void scan1_k() {
    __shared__ int sh[SCAN_CHUNK];
    int i = blockIdx.x * SCAN_CHUNK + threadIdx.x;
    sh[threadIdx.x] = (i < N_NODES) ? g_cnt[i] : 0;
    __syncthreads();
    for (int off = SCAN_CHUNK / 2; off > 0; off >>= 1) {
        if (threadIdx.x < off) sh[threadIdx.x] += sh[threadIdx.x + off];
        __syncthreads();
    }
    if (threadIdx.x == 0) g_blocksums[blockIdx.x] = sh[0];
}
__global__ void scan2_k() {
    if (threadIdx.x == 0) {
        int run = 0;
        for (int b = 0; b < SCAN_NB; b++) {
            int v = g_blocksums[b];
            g_blocksums[b] = run;
            run += v;
        }
    }
}
__global__ void scan3_k() {
    __shared__ int sh[SCAN_CHUNK];
    int i = blockIdx.x * SCAN_CHUNK + threadIdx.x;
    int v = (i < N_NODES) ? g_cnt[i] : 0;
    sh[threadIdx.x] = v;
    __syncthreads();
    for (int off = 1; off < SCAN_CHUNK; off <<= 1) {
        int t = (threadIdx.x >= off) ? sh[threadIdx.x - off] : 0;
        __syncthreads();
        sh[threadIdx.x] += t;
        __syncthreads();
    }
    if (i < N_NODES)
        g_rowptr[i] = g_blocksums[blockIdx.x] + sh[threadIdx.x] - v;
}
__global__ void scatter_k() {
    int e = blockIdx.x * blockDim.x + threadIdx.x;
    if (e >= N_EDGES) return;
    int d = g_dst[e];
    int pos = g_rowptr[d] + atomicAdd(&g_fill[d], 1);
    g_csrc[pos] = g_src[e];
}

// ---------------- gather + split-bf16 epilogue ----------------
template <int C>
__global__ __launch_bounds__(256)
void gather_split_k(const float* __restrict__ xin, __nv_bfloat16* __restrict__ aout) {
    constexpr int V = C / 128;
    int d = (blockIdx.x * blockDim.x + threadIdx.x) >> 5;
    int lane = threadIdx.x & 31;
    if (d >= N_NODES) return;
    float dd = g_dinv[d];

    float4 acc[V];
    {
        float sl = dd * dd;
        const float4* self = reinterpret_cast<const float4*>(xin + (size_t)d * C);
#pragma unroll
        for (int v = 0; v < V; v++) {
            float4 t = self[lane + v * 32];
            acc[v].x = t.x * sl; acc[v].y = t.y * sl;
            acc[v].z = t.z * sl; acc[v].w = t.w * sl;
        }
    }
    int start = g_rowptr[d];
    int cnt = g_cnt[d];
    for (int j = 0; j < cnt; j++) {
        int s = g_csrc[start + j];
        float nrm = g_dinv[s] * dd;
        const float4* xr = reinterpret_cast<const float4*>(xin + (size_t)s * C);
#pragma unroll
        for (int v = 0; v < V; v++) {
            float4 t = xr[lane + v * 32];
            acc[v].x += t.x * nrm; acc[v].y += t.y * nrm;
            acc[v].z += t.z * nrm; acc[v].w += t.w * nrm;
        }
    }
    size_t base = (size_t)d * (3 * C);
#pragma unroll
    for (int v = 0; v < V; v++) {
        int col = (lane + v * 32) * 4;
        float vals[4] = {acc[v].x, acc[v].y, acc[v].z, acc[v].w};
        __nv_bfloat16 hi[4], lo[4];
#pragma unroll
        for (int t = 0; t < 4; t++) {
            hi[t] = __float2bfloat16(vals[t]);
            lo[t] = __float2bfloat16(vals[t] - __bfloat162float(hi[t]));
        }
        __nv_bfloat162 h01 = __halves2bfloat162(hi[0], hi[1]);
        __nv_bfloat162 h23 = __halves2bfloat162(hi[2], hi[3]);
        __nv_bfloat162 l01 = __halves2bfloat162(lo[0], lo[1]);
        __nv_bfloat162 l23 = __halves2bfloat162(lo[2], lo[3]);
        *reinterpret_cast<__nv_bfloat162*>(&aout[base + col])             = h01;
        *reinterpret_cast<__nv_bfloat162*>(&aout[base + col + 2])         = h23;
        *reinterpret_cast<__nv_bfloat162*>(&aout[base + C + col])         = h01;
        *reinterpret_cast<__nv_bfloat162*>(&aout[base + C + col + 2])     = h23;
        *reinterpret_cast<__nv_bfloat162*>(&aout[base + 2 * C + col])     = l01;
        *reinterpret_cast<__nv_bfloat162*>(&aout[base + 2 * C + col + 2]) = l23;
    }
}

// ---------------- weight split + TRANSPOSE: Wt[n][3K], rows n-major ----------------
// Wt[n][k]=hi(W[k][n]); Wt[n][K+k]=lo; Wt[n][2K+k]=hi
__global__ void split_wt_k(const float* __restrict__ W, __nv_bfloat16* __restrict__ Wt,
                           int K, int Nn) {
    int idx = blockIdx.x * blockDim.x + threadIdx.x;
    if (idx >= K * Nn) return;
    int k = idx / Nn, n = idx % Nn;
    float v = W[idx];
    __nv_bfloat16 hi = __float2bfloat16(v);
    __nv_bfloat16 lo = __float2bfloat16(v - __bfloat162float(hi));
    size_t base = (size_t)n * (3 * K);
    Wt[base + k]         = hi;
    Wt[base + K + k]     = lo;
    Wt[base + 2 * K + k] = hi;
}
__global__ void logits_init_k(const float* __restrict__ bd2) {
    size_t idx = (size_t)blockIdx.x * blockDim.x + threadIdx.x;
    if (idx < (size_t)N_NODES * 6)
        g_logits[idx] = bd2[idx % 6];
}

// ============ unified cp.async double-buffered split-bf16 GEMM ============
// A2 [M][DKt] row-major bf16; Wt [Nn][DKt] row-major bf16 (n-major).
// block tile 128x128, 16 warps (4m x 4n), warp tile 32x32.
// DENSE_EPI: fuse bias+leaky+Wd2 contraction -> logits; else write fp32 C.
#define SROW 40   // smem row stride in bf16 (80B: 16B-aligned, conflict-free lds)

template <bool DENSE_EPI>
__global__ __launch_bounds__(512)
void gemm_pipe_k(const __nv_bfloat16* __restrict__ A2,
                 const __nv_bfloat16* __restrict__ Wt,
                 float* __restrict__ Cout,        // fp32 C (generic) or logits (dense)
                 const float* __restrict__ bd1,   // dense only
                 const float* __restrict__ Wd2,   // dense only
                 int M, int Nn, int DKt) {
    __shared__ __nv_bfloat16 As[2][128 * SROW];
    __shared__ __nv_bfloat16 Bs[2][128 * SROW];
    __shared__ float W2s[128][6];
    __shared__ float b1s[128];
    __shared__ float rowacc[128][6];

    const int tid  = threadIdx.x;
    const int warp = tid >> 5, lane = tid & 31;
    const int g = lane >> 2, tig = lane & 3;
    const int wm = (warp >> 2) * 32, wn = (warp & 3) * 32;
    const int rowBase = blockIdx.y * 128;
    const int n0 = blockIdx.x * 128;

    if (DENSE_EPI) {
        for (int i = tid; i < 768; i += 512) {
            W2s[i / 6][i % 6] = Wd2[(size_t)(n0 + i / 6) * 6 + (i % 6)];
            ((float*)rowacc)[i] = 0.f;
        }
        for (int i = tid; i < 128; i += 512) b1s[i] = bd1[n0 + i];
    }

    // per-thread load slot: row = tid>>2 (0..127), chunk = tid&3 (16B each)
    const int ldRow = tid >> 2, ldCh = (tid & 3) * 8;   // ldCh in bf16 units
    const int gmA = rowBase + ldRow;
    const int okA = (gmA < M) ? 16 : 0;
    const __nv_bfloat16* srcArow = A2 + (size_t)(okA ? gmA : 0) * DKt + ldCh;
    const __nv_bfloat16* srcBrow = Wt + (size_t)(n0 + ldRow) * DKt + ldCh;
    uint32_t dstA = (uint32_t)__cvta_generic_to_shared(&As[0][ldRow * SROW + ldCh]);
    uint32_t dstB = (uint32_t)__cvta_generic_to_shared(&Bs[0][ldRow * SROW + ldCh]);
    const uint32_t stageBytes = 128 * SROW * 2;

    const int nIter = DKt / 32;

    // prefetch stage 0
    cpa16(dstA, srcArow, okA);
    cpa16(dstB, srcBrow, 16);
    cpa_commit();

    float acc[2][4][4];
#pragma unroll
    for (int s = 0; s < 2; s++)
#pragma unroll
        for (int j = 0; j < 4; j++)
#pragma unroll
            for (int c = 0; c < 4; c++) acc[s][j][c] = 0.f;

    for (int it = 0; it < nIter; it++) {
        int cur = it & 1;
        if (it + 1 < nIter) {
            int nk = (it + 1) * 32;
            int nxt = (it + 1) & 1;
            cpa16(dstA + nxt * stageBytes, srcArow + nk, okA);
            cpa16(dstB + nxt * stageBytes, srcBrow + nk, 16);
            cpa_commit();
            cpa_wait<1>();
        } else {
            cpa_wait<0>();
        }
        __syncthreads();

        const __nv_bfloat16* Ac = As[cur];
        const __nv_bfloat16* Bc = Bs[cur];
#pragma unroll
        for (int kk = 0; kk < 32; kk += 16) {
            uint32_t a[2][4], b[4][2];
#pragma unroll
            for (int s = 0; s < 2; s++) {
                a[s][0] = *reinterpret_cast<const uint32_t*>(&Ac[(wm + s * 16 + g) * SROW + kk + tig * 2]);
                a[s][1] = *reinterpret_cast<const uint32_t*>(&Ac[(wm + s * 16 + 8 + g) * SROW + kk + tig * 2]);
                a[s][2] = *reinterpret_cast<const uint32_t*>(&Ac[(wm + s * 16 + g) * SROW + kk + 8 + tig * 2]);
                a[s][3] = *reinterpret_cast<const uint32_t*>(&Ac[(wm + s * 16 + 8 + g) * SROW + kk + 8 + tig * 2]);
            }
#pragma unroll
            for (int j = 0; j < 4; j++) {
                b[j][0] = *reinterpret_cast<const uint32_t*>(&Bc[(wn + j * 8 + g) * SROW + kk + tig * 2]);
                b[j][1] = *reinterpret_cast<const uint32_t*>(&Bc[(wn + j * 8 + g) * SROW + kk + 8 + tig * 2]);
            }
#pragma unroll
            for (int s = 0; s < 2; s++)
#pragma unroll
                for (int j = 0; j < 4; j++)
                    asm volatile(
                        "mma.sync.aligned.m16n8k16.row.col.f32.bf16.bf16.f32 "
                        "{%0,%1,%2,%3}, {%4,%5,%6,%7}, {%8,%9}, {%0,%1,%2,%3};"
                        : "+f"(acc[s][j][0]), "+f"(acc[s][j][1]),
                          "+f"(acc[s][j][2]), "+f"(acc[s][j][3])
                        : "r"(a[s][0]), "r"(a[s][1]), "r"(a[s][2]), "r"(a[s][3]),
                          "r"(b[j][0]), "r"(b[j][1]));
        }
        __syncthreads();
    }

    if (!DENSE_EPI) {
#pragma unroll
        for (int s = 0; s < 2; s++) {
            int r0 = rowBase + wm + s * 16 + g;
            int r1 = r0 + 8;
#pragma unroll
            for (int j = 0; j < 4; j++) {
                int col = n0 + wn + j * 8 + 2 * tig;
                if (r0 < M) {
                    Cout[(size_t)r0 * Nn + col]     = acc[s][j][0];
                    Cout[(size_t)r0 * Nn + col + 1] = acc[s][j][1];
                }
                if (r1 < M) {
                    Cout[(size_t)r1 * Nn + col]     = acc[s][j][2];
                    Cout[(size_t)r1 * Nn + col + 1] = acc[s][j][3];
                }
            }
        }
    } else {
        float acc6[4][6];
#pragma unroll
        for (int r = 0; r < 4; r++)
#pragma unroll
            for (int c = 0; c < 6; c++) acc6[r][c] = 0.f;

#pragma unroll
        for (int s = 0; s < 2; s++)
#pragma unroll
            for (int j = 0; j < 4; j++) {
                int col = wn + j * 8 + 2 * tig;
                float b0 = b1s[col], b1 = b1s[col + 1];
                float t;
                t = acc[s][j][0] + b0; t = t >= 0.f ? t : SLOPE * t;
#pragma unroll
                for (int c = 0; c < 6; c++) acc6[s * 2 + 0][c] += t * W2s[col][c];
                t = acc[s][j][1] + b1; t = t >= 0.f ? t : SLOPE * t;
#pragma unroll
                for (int c = 0; c < 6; c++) acc6[s * 2 + 0][c] += t * W2s[col + 1][c];
                t = acc[s][j][2] + b0; t = t >= 0.f ? t : SLOPE * t;
#pragma unroll
                for (int c = 0; c < 6; c++) acc6[s * 2 + 1][c] += t * W2s[col][c];
                t = acc[s][j][3] + b1; t = t >= 0.f ? t : SLOPE * t;
#pragma unroll
                for (int c = 0; c < 6; c++) acc6[s * 2 + 1][c] += t * W2s[col + 1][c];
            }

#pragma unroll
        for (int s = 0; s < 2; s++) {
            int r0 = wm + s * 16 + g;
            int r1 = wm + s * 16 + 8 + g;
#pragma unroll
            for (int c = 0; c < 6; c++) {
                atomicAdd(&rowacc[r0][c], acc6[s * 2 + 0][c]);
                atomicAdd(&rowacc[r1][c], acc6[s * 2 + 1][c]);
            }
        }
        __syncthreads();
        for (int i = tid; i < 768; i += 512) {
            int r = i / 6, c = i % 6;
            if (rowBase + r < M)
                atomicAdd(&Cout[(size_t)(rowBase + r) * 6 + c], rowacc[r][c]);
        }
    }
}

// ---------------- BatchNorm ----------------
__global__ void bn_zero_k(int C) {
    int c = threadIdx.x + blockIdx.x * blockDim.x;
    if (c < C) { g_colsum[c] = 0.f; g_colsq[c] = 0.f; }
}
template <int C>
__global__ void bn_reduce_k(const float* __restrict__ h) {
    int c = threadIdx.x;
    int rows_per = (N_NODES + gridDim.x - 1) / gridDim.x;
    int r0 = blockIdx.x * rows_per;
    int r1 = min(r0 + rows_per, N_NODES);
    float s = 0.f, sq = 0.f;
    for (int r = r0; r < r1; r++) {
        float v = h[(size_t)r * C + c];
        s += v; sq += v * v;
    }
    atomicAdd(&g_colsum[c], s);
    atomicAdd(&g_colsq[c], sq);
}
__global__ void bn_scale_k(const float* __restrict__ g, const float* __restrict__ be, int C) {
    int c = threadIdx.x + blockIdx.x * blockDim.x;
    if (c < C) {
        float mean = g_colsum[c] * (1.0f / N_NODES);
        float var  = g_colsq[c] * (1.0f / N_NODES) - mean * mean;
        float a = g[c] * rsqrtf(var + BN_EPS);
        g_scale[c] = a;
        g_shift[c] = be[c] - mean * a;
    }
}
template <int C>
__global__ void bn_apply_k(float* __restrict__ h) {
    size_t idx = (size_t)blockIdx.x * blockDim.x + threadIdx.x;
    if (idx < (size_t)N_NODES * C) {
        int c = (int)(idx & (C - 1));
        float v = h[idx] * g_scale[c] + g_shift[c];
        h[idx] = v >= 0.f ? v : SLOPE * v;
    }
}

// ---------------- fused BN-apply + leaky + split ----------------
__global__ void split_a_fused_k(const float* __restrict__ h2raw, __nv_bfloat16* __restrict__ a2) {
    size_t idx = (size_t)blockIdx.x * blockDim.x + threadIdx.x;
    if (idx >= (size_t)N_NODES * 512) return;
    int m = (int)(idx >> 9), k = (int)(idx & 511);
    float v = h2raw[idx] * g_scale[k] + g_shift[k];
    v = v >= 0.f ? v : SLOPE * v;
    __nv_bfloat16 hi = __float2bfloat16(v);
    __nv_bfloat16 lo = __float2bfloat16(v - __bfloat162float(hi));
    size_t base = (size_t)m * DK;
    a2[base + k]        = hi;
    a2[base + 512 + k]  = hi;
    a2[base + 1024 + k] = lo;
}

// ---------------- softmax ----------------
__global__ void softmax_k(const float* __restrict__ logits, float* __restrict__ out) {
    int r = blockIdx.x * blockDim.x + threadIdx.x;
    if (r >= N_NODES) return;
    float v[6];
    float m = -1e30f;
#pragma unroll
    for (int j = 0; j < 6; j++) { v[j] = logits[(size_t)r * 6 + j]; m = fmaxf(m, v[j]); }
    float ssum = 0.f;
#pragma unroll
    for (int j = 0; j < 6; j++) { v[j] = __expf(v[j] - m); ssum += v[j]; }
    float inv = 1.0f / ssum;
#pragma unroll
    for (int j = 0; j < 6; j++) out[(size_t)r * 6 + j] = v[j] * inv;
}

// ---------------- launch ----------------
static inline void* symp(const void* s) {
    void* p = nullptr;
    cudaGetSymbolAddress(&p, s);
    return p;
}

extern "C" void kernel_launch(void* const* d_in, const int* in_sizes, int n_in,
                              void* d_out, int out_size) {
    const float* x    = (const float*)d_in[0];
    const void*  ei   = d_in[1];
    const float* W1   = (const float*)d_in[2];
    const float* W2   = (const float*)d_in[4];
    const float* g1   = (const float*)d_in[6];
    const float* be1  = (const float*)d_in[7];
    const float* g2   = (const float*)d_in[8];
    const float* be2  = (const float*)d_in[9];
    const float* Wd1  = (const float*)d_in[10];
    const float* bd1  = (const float*)d_in[11];
    const float* Wd2  = (const float*)d_in[12];
    const float* bd2  = (const float*)d_in[13];
    float*       out  = (float*)d_out;

    unsigned char* arena = (unsigned char*)symp(g_arena);
    __nv_bfloat16* ga1 = (__nv_bfloat16*)arena;                                 // N*384
    __nv_bfloat16* ga2 = (__nv_bfloat16*)(arena + (size_t)N_NODES * 384 * 2);   // N*768
    __nv_bfloat16* a2  = (__nv_bfloat16*)arena;                                 // N*1536
    float* h1  = (float*)symp(g_h1);
    float* h2  = (float*)symp(g_h2);
    float* lg  = (float*)symp(g_logits);
    __nv_bfloat16* wd  = (__nv_bfloat16*)symp(g_wd);
    __nv_bfloat16* w1s = (__nv_bfloat16*)symp(g_w1s);
    __nv_bfloat16* w2s = (__nv_bfloat16*)symp(g_w2s);

    // edge conversion + CSR build
    detect_k<<<1, 256>>>((const unsigned long long*)ei);
    cvt_edges_k<<<(N_EDGES + 255) / 256, 256>>>(ei);
    cnt_zero_k<<<(N_NODES + 255) / 256, 256>>>();
    deg_count_k<<<(N_EDGES + 255) / 256, 256>>>();
    dinv_k<<<(N_NODES + 255) / 256, 256>>>();
    scan1_k<<<SCAN_NB, SCAN_CHUNK>>>();
    scan2_k<<<1, 32>>>();
    scan3_k<<<SCAN_NB, SCAN_CHUNK>>>();
    scatter_k<<<(N_EDGES + 255) / 256, 256>>>();

    // weight prep (independent; transposed split layout)
    split_wt_k<<<(int)(((size_t)512 * 4096 + 255) / 256), 256>>>(Wd1, wd, 512, 4096);
    split_wt_k<<<(128 * 256 + 255) / 256, 256>>>(W1, w1s, 128, 256);
    split_wt_k<<<(256 * 512 + 255) / 256, 256>>>(W2, w2s, 256, 512);
    logits_init_k<<<(N_NODES * 6 + 255) / 256, 256>>>(bd2);

    // ---- layer 1: gather(x) -> GEMM -> BN + LeakyReLU ----
    gather_split_k<128><<<(int)(((size_t)N_NODES * 32 + 255) / 256), 256>>>(x, ga1);
    {
        dim3 grid(256 / 128, (N_NODES + 127) / 128);
        gemm_pipe_k<false><<<grid, 512>>>(ga1, w1s, h1, nullptr, nullptr, N_NODES, 256, 384);
    }
    bn_zero_k<<<2, 256>>>(256);
    bn_reduce_k<256><<<512, 256>>>(h1);
    bn_scale_k<<<1, 256>>>(g1, be1, 256);
    bn_apply_k<256><<<(int)(((size_t)N_NODES * 256 + 255) / 256), 256>>>(h1);

    // ---- layer 2: gather(h1) -> GEMM -> BN stats (apply fused into split) ----
    gather_split_k<256><<<(int)(((size_t)N_NODES * 32 + 255) / 256), 256>>>(h1, ga2);
    {
        dim3 grid(512 / 128, (N_NODES + 127) / 128);
        gemm_pipe_k<false><<<grid, 512>>>(ga2, w2s, h2, nullptr, nullptr, N_NODES, 512, 768);
    }
    bn_zero_k<<<2, 256>>>(512);
    bn_reduce_k<512><<<512, 512>>>(h2);
    bn_scale_k<<<2, 256>>>(g2, be2, 512);

    // ---- fused BN-apply + leaky + split (h2raw -> a2) ----
    split_a_fused_k<<<(int)(((size_t)N_NODES * 512 + 255) / 256), 256>>>(h2, a2);

    // ---- dense1 (pipelined tensor core) + LeakyReLU + dense2 partials ----
    {
        dim3 grid(4096 / 128, (N_NODES + 127) / 128);
        gemm_pipe_k<true><<<grid, 512>>>(a2, wd, lg, bd1, Wd2, N_NODES, 4096, DK);
    }

    // ---- softmax ----
    softmax_k<<<(N_NODES + 255) / 256, 256>>>(lg, out);
}